// round 4
// baseline (speedup 1.0000x reference)
#include <cuda_runtime.h>
#include <math.h>

#define NN    100000
#define DIM   128
#define HEADS 8
#define HD    16
#define NE    1600000
#define NEG   0.2f
#define LNEPS 1e-5f
#define HID   512
#define GB_ROWS 782   // ceil(NN/128)

// ---------------- scratch (static device globals; no allocation) -------------
__device__ float g_h   [(size_t)NN * DIM];   // x @ W_gat
__device__ float g_z   [(size_t)NN * HID];   // FFN hidden
__device__ float g_asrc[NN * HEADS];
__device__ float g_adst[NN * HEADS];
__device__ int   g_counts [NN];
__device__ int   g_cursors[NN];
__device__ int   g_offsets[NN + 1];
__device__ int   g_csr[NE];
__device__ int   g_is64;

// ---------------- edge dtype detection ---------------------------------------
// If edge_index is really int64 (values < 2^31), every high 32-bit word is 0.
// If it is int32 (JAX x64 disabled), those words are random node ids.
__global__ void k_detect(const unsigned int* __restrict__ ew) {
    if (threadIdx.x == 0 && blockIdx.x == 0) {
        unsigned int acc = 0;
        #pragma unroll
        for (int i = 0; i < 16; ++i) acc |= ew[2 * i + 1];
        g_is64 = (acc == 0) ? 1 : 0;
    }
}

// ---------------- CSR build --------------------------------------------------
__global__ void k_zero_int() {
    int i = blockIdx.x * blockDim.x + threadIdx.x;
    if (i < NN) { g_counts[i] = 0; g_cursors[i] = 0; }
}

__device__ __forceinline__ int edge_at(const void* ei, int is64, size_t idx) {
    if (is64) return (int)((const long long*)ei)[idx];
    return ((const int*)ei)[idx];
}

__global__ void k_hist(const void* __restrict__ ei) {
    int i = blockIdx.x * blockDim.x + threadIdx.x;
    if (i >= NE) return;
    const int is64 = g_is64;
    int dst = edge_at(ei, is64, (size_t)NE + i);
    if ((unsigned)dst < (unsigned)NN) atomicAdd(&g_counts[dst], 1);
}

__global__ void k_scan() {
    __shared__ int sh[1024];
    const int t = threadIdx.x;
    const int C = (NN + 1023) / 1024;
    int lo = t * C;
    int hi = lo + C; if (hi > NN) hi = NN;
    int local = 0;
    for (int i = lo; i < hi; ++i) local += g_counts[i];
    sh[t] = local;
    __syncthreads();
    for (int off = 1; off < 1024; off <<= 1) {
        int v = (t >= off) ? sh[t - off] : 0;
        __syncthreads();
        sh[t] += v;
        __syncthreads();
    }
    int run = (t > 0) ? sh[t - 1] : 0;
    for (int i = lo; i < hi; ++i) { g_offsets[i] = run; run += g_counts[i]; }
    if (t == 1023) g_offsets[NN] = sh[1023];
}

__global__ void k_scatter(const void* __restrict__ ei) {
    int i = blockIdx.x * blockDim.x + threadIdx.x;
    if (i >= NE) return;
    const int is64 = g_is64;
    int src = edge_at(ei, is64, i);
    int dst = edge_at(ei, is64, (size_t)NE + i);
    if ((unsigned)src < (unsigned)NN && (unsigned)dst < (unsigned)NN) {
        int pos = g_offsets[dst] + atomicAdd(&g_cursors[dst], 1);
        g_csr[pos] = src;
    }
}

// ---------------- GEMM 1: g_h = x @ Wg, epilogue computes a_src/a_dst --------
__global__ __launch_bounds__(256) void k_gemm_h(
    const float* __restrict__ x, const float* __restrict__ Wg,
    const float* __restrict__ att_s, const float* __restrict__ att_d)
{
    __shared__ float As[16][132];   // As[kk][m]
    __shared__ float Bs[16][128];   // Bs[kk][n]
    const int tid = threadIdx.x;
    const int tx  = tid & 15;
    const int ty  = tid >> 4;
    const int rowBase = blockIdx.x * 128;

    float acc[8][8];
    #pragma unroll
    for (int i = 0; i < 8; ++i)
        #pragma unroll
        for (int j = 0; j < 8; ++j) acc[i][j] = 0.f;

    for (int k0 = 0; k0 < DIM; k0 += 16) {
        #pragma unroll
        for (int t = 0; t < 8; ++t) {
            int idx = tid + t * 256;
            int m = idx >> 4, kk = idx & 15;
            int gr = rowBase + m;
            As[kk][m] = (gr < NN) ? x[(size_t)gr * DIM + k0 + kk] : 0.f;
        }
        #pragma unroll
        for (int t = 0; t < 8; ++t) {
            int idx = tid + t * 256;
            int kk = idx >> 7, n = idx & 127;
            Bs[kk][n] = Wg[(size_t)(k0 + kk) * DIM + n];
        }
        __syncthreads();
        #pragma unroll
        for (int kk = 0; kk < 16; ++kk) {
            float a[8], b[8];
            float4 a0 = *(const float4*)&As[kk][ty * 8];
            float4 a1 = *(const float4*)&As[kk][ty * 8 + 4];
            a[0]=a0.x; a[1]=a0.y; a[2]=a0.z; a[3]=a0.w;
            a[4]=a1.x; a[5]=a1.y; a[6]=a1.z; a[7]=a1.w;
            float4 b0 = *(const float4*)&Bs[kk][tx * 8];
            float4 b1 = *(const float4*)&Bs[kk][tx * 8 + 4];
            b[0]=b0.x; b[1]=b0.y; b[2]=b0.z; b[3]=b0.w;
            b[4]=b1.x; b[5]=b1.y; b[6]=b1.z; b[7]=b1.w;
            #pragma unroll
            for (int i = 0; i < 8; ++i)
                #pragma unroll
                for (int j = 0; j < 8; ++j)
                    acc[i][j] = fmaf(a[i], b[j], acc[i][j]);
        }
        __syncthreads();
    }

    float asv[8], adv[8];
    #pragma unroll
    for (int j = 0; j < 8; ++j) {
        asv[j] = att_s[tx * 8 + j];
        adv[j] = att_d[tx * 8 + j];
    }

    #pragma unroll
    for (int i = 0; i < 8; ++i) {
        int r = rowBase + ty * 8 + i;
        bool ok = (r < NN);
        float s1 = 0.f, s2 = 0.f;
        #pragma unroll
        for (int j = 0; j < 8; ++j) {
            float v = acc[i][j];
            s1 = fmaf(v, asv[j], s1);
            s2 = fmaf(v, adv[j], s2);
        }
        s1 += __shfl_xor_sync(0xFFFFFFFFu, s1, 1);
        s2 += __shfl_xor_sync(0xFFFFFFFFu, s2, 1);
        if (ok) {
            float4 c0 = make_float4(acc[i][0], acc[i][1], acc[i][2], acc[i][3]);
            float4 c1 = make_float4(acc[i][4], acc[i][5], acc[i][6], acc[i][7]);
            *(float4*)&g_h[(size_t)r * DIM + tx * 8]     = c0;
            *(float4*)&g_h[(size_t)r * DIM + tx * 8 + 4] = c1;
            if ((tx & 1) == 0) {
                g_asrc[r * 8 + (tx >> 1)] = s1;
                g_adst[r * 8 + (tx >> 1)] = s2;
            }
        }
    }
}

// ---------------- aggregation + residual + LN1 (1 warp / node) ---------------
__device__ __forceinline__ float leaky(float v) { return fmaxf(v, NEG * v); }

__global__ __launch_bounds__(256) void k_agg_ln(
    const float* __restrict__ x, const float* __restrict__ bg,
    const float* __restrict__ gamma, const float* __restrict__ beta,
    float* __restrict__ h1)
{
    int w = (blockIdx.x * blockDim.x + threadIdx.x) >> 5;
    if (w >= NN) return;
    const int lane = threadIdx.x & 31;

    float adst[8], asrci[8];
    {
        float4 a = *(const float4*)&g_adst[w * 8];
        float4 b = *(const float4*)&g_adst[w * 8 + 4];
        adst[0]=a.x; adst[1]=a.y; adst[2]=a.z; adst[3]=a.w;
        adst[4]=b.x; adst[5]=b.y; adst[6]=b.z; adst[7]=b.w;
        float4 c = *(const float4*)&g_asrc[w * 8];
        float4 d = *(const float4*)&g_asrc[w * 8 + 4];
        asrci[0]=c.x; asrci[1]=c.y; asrci[2]=c.z; asrci[3]=c.w;
        asrci[4]=d.x; asrci[5]=d.y; asrci[6]=d.z; asrci[7]=d.w;
    }

    const int beg = g_offsets[w];
    const int end = g_offsets[w + 1];

    float m[8];
    #pragma unroll
    for (int h = 0; h < 8; ++h) m[h] = leaky(asrci[h] + adst[h]);
    for (int j = beg + lane; j < end; j += 32) {
        int s = g_csr[j];
        float4 a = *(const float4*)&g_asrc[s * 8];
        float4 b = *(const float4*)&g_asrc[s * 8 + 4];
        m[0] = fmaxf(m[0], leaky(a.x + adst[0]));
        m[1] = fmaxf(m[1], leaky(a.y + adst[1]));
        m[2] = fmaxf(m[2], leaky(a.z + adst[2]));
        m[3] = fmaxf(m[3], leaky(a.w + adst[3]));
        m[4] = fmaxf(m[4], leaky(b.x + adst[4]));
        m[5] = fmaxf(m[5], leaky(b.y + adst[5]));
        m[6] = fmaxf(m[6], leaky(b.z + adst[6]));
        m[7] = fmaxf(m[7], leaky(b.w + adst[7]));
    }
    #pragma unroll
    for (int h = 0; h < 8; ++h)
        #pragma unroll
        for (int o = 16; o > 0; o >>= 1)
            m[h] = fmaxf(m[h], __shfl_xor_sync(0xFFFFFFFFu, m[h], o));

    const int myh = lane >> 2;
    float mm = m[0], adm = adst[0], asm_ = asrci[0];
    #pragma unroll
    for (int h = 1; h < 8; ++h)
        if (myh == h) { mm = m[h]; adm = adst[h]; asm_ = asrci[h]; }

    float l = 0.f;
    float4 acc = make_float4(0.f, 0.f, 0.f, 0.f);
    {
        float p = __expf(leaky(asm_ + adm) - mm);
        l += p;
        float4 hv = *(const float4*)&g_h[(size_t)w * DIM + lane * 4];
        acc.x += p * hv.x; acc.y += p * hv.y; acc.z += p * hv.z; acc.w += p * hv.w;
    }
    for (int j = beg; j < end; ++j) {
        int s = g_csr[j];
        float p = __expf(leaky(g_asrc[s * 8 + myh] + adm) - mm);
        l += p;
        float4 hv = *(const float4*)&g_h[(size_t)s * DIM + lane * 4];
        acc.x += p * hv.x; acc.y += p * hv.y; acc.z += p * hv.z; acc.w += p * hv.w;
    }
    float inv = 1.f / (l + 1e-16f);

    float4 xv  = *(const float4*)&x[(size_t)w * DIM + lane * 4];
    float4 bgv = *(const float4*)&bg[lane * 4];
    float4 v;
    v.x = xv.x + acc.x * inv + bgv.x;
    v.y = xv.y + acc.y * inv + bgv.y;
    v.z = xv.z + acc.z * inv + bgv.z;
    v.w = xv.w + acc.w * inv + bgv.w;

    float s = v.x + v.y + v.z + v.w;
    #pragma unroll
    for (int o = 16; o > 0; o >>= 1) s += __shfl_xor_sync(0xFFFFFFFFu, s, o);
    float mu = s * (1.f / DIM);
    v.x -= mu; v.y -= mu; v.z -= mu; v.w -= mu;
    float q = v.x * v.x + v.y * v.y + v.z * v.z + v.w * v.w;
    #pragma unroll
    for (int o = 16; o > 0; o >>= 1) q += __shfl_xor_sync(0xFFFFFFFFu, q, o);
    float rs = rsqrtf(q * (1.f / DIM) + LNEPS);
    float4 g  = *(const float4*)&gamma[lane * 4];
    float4 be = *(const float4*)&beta[lane * 4];
    float4 o4;
    o4.x = g.x * v.x * rs + be.x;
    o4.y = g.y * v.y * rs + be.y;
    o4.z = g.z * v.z * rs + be.z;
    o4.w = g.w * v.w * rs + be.w;
    *(float4*)&h1[(size_t)w * DIM + lane * 4] = o4;
}

// ---------------- FFN1: g_z = gelu(h1 @ W1 + b1) -----------------------------
__global__ __launch_bounds__(256) void k_ffn1(
    const float* __restrict__ h1, const float* __restrict__ W1,
    const float* __restrict__ b1)
{
    __shared__ float As[16][132];
    __shared__ float Bs[16][128];
    const int tid = threadIdx.x;
    const int tx  = tid & 15;
    const int ty  = tid >> 4;
    const int rowBase = blockIdx.y * 128;
    const int colBase = blockIdx.x * 128;

    float acc[8][8];
    #pragma unroll
    for (int i = 0; i < 8; ++i)
        #pragma unroll
        for (int j = 0; j < 8; ++j) acc[i][j] = 0.f;

    for (int k0 = 0; k0 < DIM; k0 += 16) {
        #pragma unroll
        for (int t = 0; t < 8; ++t) {
            int idx = tid + t * 256;
            int m = idx >> 4, kk = idx & 15;
            int gr = rowBase + m;
            As[kk][m] = (gr < NN) ? h1[(size_t)gr * DIM + k0 + kk] : 0.f;
        }
        #pragma unroll
        for (int t = 0; t < 8; ++t) {
            int idx = tid + t * 256;
            int kk = idx >> 7, n = idx & 127;
            Bs[kk][n] = W1[(size_t)(k0 + kk) * HID + colBase + n];
        }
        __syncthreads();
        #pragma unroll
        for (int kk = 0; kk < 16; ++kk) {
            float a[8], b[8];
            float4 a0 = *(const float4*)&As[kk][ty * 8];
            float4 a1 = *(const float4*)&As[kk][ty * 8 + 4];
            a[0]=a0.x; a[1]=a0.y; a[2]=a0.z; a[3]=a0.w;
            a[4]=a1.x; a[5]=a1.y; a[6]=a1.z; a[7]=a1.w;
            float4 b0 = *(const float4*)&Bs[kk][tx * 8];
            float4 b1v = *(const float4*)&Bs[kk][tx * 8 + 4];
            b[0]=b0.x; b[1]=b0.y; b[2]=b0.z; b[3]=b0.w;
            b[4]=b1v.x; b[5]=b1v.y; b[6]=b1v.z; b[7]=b1v.w;
            #pragma unroll
            for (int i = 0; i < 8; ++i)
                #pragma unroll
                for (int j = 0; j < 8; ++j)
                    acc[i][j] = fmaf(a[i], b[j], acc[i][j]);
        }
        __syncthreads();
    }

    float bv[8];
    #pragma unroll
    for (int j = 0; j < 8; ++j) bv[j] = b1[colBase + tx * 8 + j];

    #pragma unroll
    for (int i = 0; i < 8; ++i) {
        int r = rowBase + ty * 8 + i;
        if (r >= NN) continue;
        float4 o0, o1;
        float t0 = acc[i][0] + bv[0], t1 = acc[i][1] + bv[1];
        float t2 = acc[i][2] + bv[2], t3 = acc[i][3] + bv[3];
        float t4 = acc[i][4] + bv[4], t5 = acc[i][5] + bv[5];
        float t6 = acc[i][6] + bv[6], t7 = acc[i][7] + bv[7];
        o0.x = 0.5f * t0 * (1.0f + erff(t0 * 0.70710678f));
        o0.y = 0.5f * t1 * (1.0f + erff(t1 * 0.70710678f));
        o0.z = 0.5f * t2 * (1.0f + erff(t2 * 0.70710678f));
        o0.w = 0.5f * t3 * (1.0f + erff(t3 * 0.70710678f));
        o1.x = 0.5f * t4 * (1.0f + erff(t4 * 0.70710678f));
        o1.y = 0.5f * t5 * (1.0f + erff(t5 * 0.70710678f));
        o1.z = 0.5f * t6 * (1.0f + erff(t6 * 0.70710678f));
        o1.w = 0.5f * t7 * (1.0f + erff(t7 * 0.70710678f));
        *(float4*)&g_z[(size_t)r * HID + colBase + tx * 8]     = o0;
        *(float4*)&g_z[(size_t)r * HID + colBase + tx * 8 + 4] = o1;
    }
}

// ---------------- FFN2 + residual + LN2: io = LN(io + g_z @ W2 + b2) ---------
__global__ __launch_bounds__(256) void k_ffn2(
    const float* __restrict__ W2, const float* __restrict__ b2,
    const float* __restrict__ gamma, const float* __restrict__ beta,
    float* __restrict__ io)
{
    __shared__ float As[16][132];
    __shared__ float Bs[16][128];
    const int tid = threadIdx.x;
    const int tx  = tid & 15;
    const int ty  = tid >> 4;
    const int rowBase = blockIdx.x * 128;

    float acc[8][8];
    #pragma unroll
    for (int i = 0; i < 8; ++i)
        #pragma unroll
        for (int j = 0; j < 8; ++j) acc[i][j] = 0.f;

    for (int k0 = 0; k0 < HID; k0 += 16) {
        #pragma unroll
        for (int t = 0; t < 8; ++t) {
            int idx = tid + t * 256;
            int m = idx >> 4, kk = idx & 15;
            int gr = rowBase + m;
            As[kk][m] = (gr < NN) ? g_z[(size_t)gr * HID + k0 + kk] : 0.f;
        }
        #pragma unroll
        for (int t = 0; t < 8; ++t) {
            int idx = tid + t * 256;
            int kk = idx >> 7, n = idx & 127;
            Bs[kk][n] = W2[(size_t)(k0 + kk) * DIM + n];
        }
        __syncthreads();
        #pragma unroll
        for (int kk = 0; kk < 16; ++kk) {
            float a[8], b[8];
            float4 a0 = *(const float4*)&As[kk][ty * 8];
            float4 a1 = *(const float4*)&As[kk][ty * 8 + 4];
            a[0]=a0.x; a[1]=a0.y; a[2]=a0.z; a[3]=a0.w;
            a[4]=a1.x; a[5]=a1.y; a[6]=a1.z; a[7]=a1.w;
            float4 b0 = *(const float4*)&Bs[kk][tx * 8];
            float4 b1v = *(const float4*)&Bs[kk][tx * 8 + 4];
            b[0]=b0.x; b[1]=b0.y; b[2]=b0.z; b[3]=b0.w;
            b[4]=b1v.x; b[5]=b1v.y; b[6]=b1v.z; b[7]=b1v.w;
            #pragma unroll
            for (int i = 0; i < 8; ++i)
                #pragma unroll
                for (int j = 0; j < 8; ++j)
                    acc[i][j] = fmaf(a[i], b[j], acc[i][j]);
        }
        __syncthreads();
    }

    float bv[8], gv[8], bev[8];
    #pragma unroll
    for (int j = 0; j < 8; ++j) {
        bv[j]  = b2[tx * 8 + j];
        gv[j]  = gamma[tx * 8 + j];
        bev[j] = beta[tx * 8 + j];
    }

    #pragma unroll
    for (int i = 0; i < 8; ++i) {
        int r = rowBase + ty * 8 + i;
        bool ok = (r < NN);
        float hv[8];
        if (ok) {
            float4 h0  = *(const float4*)&io[(size_t)r * DIM + tx * 8];
            float4 h1v = *(const float4*)&io[(size_t)r * DIM + tx * 8 + 4];
            hv[0]=h0.x; hv[1]=h0.y; hv[2]=h0.z; hv[3]=h0.w;
            hv[4]=h1v.x; hv[5]=h1v.y; hv[6]=h1v.z; hv[7]=h1v.w;
        } else {
            #pragma unroll
            for (int j = 0; j < 8; ++j) hv[j] = 0.f;
        }
        float v[8];
        float s = 0.f;
        #pragma unroll
        for (int j = 0; j < 8; ++j) { v[j] = acc[i][j] + bv[j] + hv[j]; s += v[j]; }
        #pragma unroll
        for (int o = 8; o > 0; o >>= 1) s += __shfl_xor_sync(0xFFFFFFFFu, s, o, 16);
        float mu = s * (1.f / DIM);
        float q = 0.f;
        #pragma unroll
        for (int j = 0; j < 8; ++j) { v[j] -= mu; q += v[j] * v[j]; }
        #pragma unroll
        for (int o = 8; o > 0; o >>= 1) q += __shfl_xor_sync(0xFFFFFFFFu, q, o, 16);
        float rs = rsqrtf(q * (1.f / DIM) + LNEPS);
        if (ok) {
            float4 o0, o1;
            o0.x = gv[0]*v[0]*rs + bev[0];
            o0.y = gv[1]*v[1]*rs + bev[1];
            o0.z = gv[2]*v[2]*rs + bev[2];
            o0.w = gv[3]*v[3]*rs + bev[3];
            o1.x = gv[4]*v[4]*rs + bev[4];
            o1.y = gv[5]*v[5]*rs + bev[5];
            o1.z = gv[6]*v[6]*rs + bev[6];
            o1.w = gv[7]*v[7]*rs + bev[7];
            *(float4*)&io[(size_t)r * DIM + tx * 8]     = o0;
            *(float4*)&io[(size_t)r * DIM + tx * 8 + 4] = o1;
        }
    }
}

// ---------------- launcher (kernel launches ONLY) ----------------------------
extern "C" void kernel_launch(void* const* d_in, const int* in_sizes, int n_in,
                              void* d_out, int out_size)
{
    const float* x     = (const float*)d_in[0];
    const void*  ei    = d_in[1];                 // int32 or int64 (detected)
    const float* Wg    = (const float*)d_in[2];
    const float* att_s = (const float*)d_in[3];
    const float* att_d = (const float*)d_in[4];
    const float* bg    = (const float*)d_in[5];
    const float* gamma = (const float*)d_in[6];
    const float* beta  = (const float*)d_in[7];
    const float* W1    = (const float*)d_in[8];
    const float* b1    = (const float*)d_in[9];
    const float* W2    = (const float*)d_in[10];
    const float* b2    = (const float*)d_in[11];
    float*       out   = (float*)d_out;

    // dtype detection + CSR build
    k_detect<<<1, 32>>>((const unsigned int*)ei);
    k_zero_int<<<(NN + 255) / 256, 256>>>();
    k_hist<<<(NE + 255) / 256, 256>>>(ei);
    k_scan<<<1, 1024>>>();
    k_scatter<<<(NE + 255) / 256, 256>>>(ei);

    // h = x @ W_gat (+ attention coefficients in epilogue)
    k_gemm_h<<<GB_ROWS, 256>>>(x, Wg, att_s, att_d);
    // h1 = LN(x + GAT_agg + b_gat) -> d_out
    k_agg_ln<<<(NN * 32 + 255) / 256, 256>>>(x, bg, gamma, beta, out);
    // z = gelu(h1 @ W1 + b1)
    k_ffn1<<<dim3(HID / 128, GB_ROWS), 256>>>(out, W1, b1);
    // out = LN(h1 + z @ W2 + b2)
    k_ffn2<<<GB_ROWS, 256>>>(W2, b2, gamma, beta, out);
}

// round 5
// speedup vs baseline: 1.6266x; 1.6266x over previous
#include <cuda_runtime.h>
#include <cuda_bf16.h>
#include <math.h>

#define NN    100000
#define DIM   128
#define HEADS 8
#define NE    1600000
#define NEG   0.2f
#define LNEPS 1e-5f
#define HID   512
#define GB_ROWS 782            // ceil(NN/128)
#define SCAN_NB 98             // ceil(NN/1024)

#define OFF_WG 0
#define OFF_W1 16384           // 128*128
#define OFF_W2 81920           // + 128*512
#define WTOT   147456          // + 512*128

// ---------------- scratch (static device globals; no allocation) -------------
__device__ float          g_h   [(size_t)NN * DIM];   // x@Wg, later FFN2 out
__device__ float          g_z   [(size_t)NN * HID];   // FFN hidden
__device__ float          g_asrc[NN * HEADS];
__device__ float          g_adst[NN * HEADS];
__device__ __nv_bfloat16  g_wThi[WTOT];               // W^T hi  [n][k]
__device__ __nv_bfloat16  g_wTlo[WTOT];               // W^T lo  [n][k]
__device__ int            g_counts  [NN];
__device__ int            g_cursors [NN];
__device__ int            g_offsets [NN + 1];
__device__ int            g_csr     [NE];
__device__ int            g_blocksum[SCAN_NB];
__device__ int            g_blockoff[SCAN_NB];
__device__ int            g_is64;

// ---------------- edge dtype detection ---------------------------------------
__global__ void k_detect(const unsigned int* __restrict__ ew) {
    if (threadIdx.x == 0 && blockIdx.x == 0) {
        unsigned int acc = 0;
        #pragma unroll
        for (int i = 0; i < 16; ++i) acc |= ew[2 * i + 1];
        g_is64 = (acc == 0) ? 1 : 0;
    }
}

// ---------------- CSR build --------------------------------------------------
__global__ void k_zero_int() {
    int i = blockIdx.x * blockDim.x + threadIdx.x;
    if (i < NN) { g_counts[i] = 0; g_cursors[i] = 0; }
}

__device__ __forceinline__ int edge_at(const void* ei, int is64, size_t idx) {
    if (is64) return (int)((const long long*)ei)[idx];
    return ((const int*)ei)[idx];
}

__global__ void k_hist(const void* __restrict__ ei) {
    int i = blockIdx.x * blockDim.x + threadIdx.x;
    if (i >= NE) return;
    int dst = edge_at(ei, g_is64, (size_t)NE + i);
    if ((unsigned)dst < (unsigned)NN) atomicAdd(&g_counts[dst], 1);
}

// multi-block scan: part -> tops -> add
__global__ __launch_bounds__(1024) void k_scan_part() {
    __shared__ int ws[32];
    int tid = threadIdx.x;
    int i = blockIdx.x * 1024 + tid;
    int v = (i < NN) ? g_counts[i] : 0;
    int lane = tid & 31, wid = tid >> 5;
    int x = v;
    #pragma unroll
    for (int o = 1; o < 32; o <<= 1) {
        int y = __shfl_up_sync(0xFFFFFFFFu, x, o);
        if (lane >= o) x += y;
    }
    if (lane == 31) ws[wid] = x;
    __syncthreads();
    if (wid == 0) {
        int s = ws[lane];
        #pragma unroll
        for (int o = 1; o < 32; o <<= 1) {
            int y = __shfl_up_sync(0xFFFFFFFFu, s, o);
            if (lane >= o) s += y;
        }
        ws[lane] = s;
    }
    __syncthreads();
    int base = wid ? ws[wid - 1] : 0;
    int incl = base + x;
    if (i < NN) g_offsets[i] = incl - v;           // block-local exclusive
    if (tid == 1023) g_blocksum[blockIdx.x] = incl;
}

__global__ void k_scan_tops() {
    __shared__ int ws[4];
    int t = threadIdx.x;                            // 128 threads
    int v = (t < SCAN_NB) ? g_blocksum[t] : 0;
    int lane = t & 31, wid = t >> 5;
    int x = v;
    #pragma unroll
    for (int o = 1; o < 32; o <<= 1) {
        int y = __shfl_up_sync(0xFFFFFFFFu, x, o);
        if (lane >= o) x += y;
    }
    if (lane == 31) ws[wid] = x;
    __syncthreads();
    int add = 0;
    for (int w = 0; w < wid; ++w) add += ws[w];
    x += add;
    if (t < SCAN_NB) g_blockoff[t] = x - v;         // exclusive
    if (t == SCAN_NB - 1) g_offsets[NN] = x;        // grand total
}

__global__ __launch_bounds__(1024) void k_scan_add() {
    int i = blockIdx.x * 1024 + threadIdx.x;
    if (i < NN) g_offsets[i] += g_blockoff[blockIdx.x];
}

__global__ void k_scatter(const void* __restrict__ ei) {
    int i = blockIdx.x * blockDim.x + threadIdx.x;
    if (i >= NE) return;
    int src = edge_at(ei, g_is64, i);
    int dst = edge_at(ei, g_is64, (size_t)NE + i);
    if ((unsigned)src < (unsigned)NN && (unsigned)dst < (unsigned)NN) {
        int pos = g_offsets[dst] + atomicAdd(&g_cursors[dst], 1);
        g_csr[pos] = src;
    }
}

// ---------------- weight convert + transpose (fp32 [k][n] -> bf16 split [n][k])
__global__ void k_convT(const float* __restrict__ src, int K, int N, int off) {
    int i = blockIdx.x * blockDim.x + threadIdx.x;
    if (i >= K * N) return;
    int k = i / N, n = i % N;
    float v = src[i];
    __nv_bfloat16 h = __float2bfloat16(v);
    __nv_bfloat16 l = __float2bfloat16(v - __bfloat162float(h));
    g_wThi[off + n * K + k] = h;
    g_wTlo[off + n * K + k] = l;
}

// ---------------- bf16x3 tensor-core GEMM body --------------------------------
__device__ __forceinline__ void mma_bf16(float* c, const unsigned* a,
                                         unsigned b0, unsigned b1) {
    asm volatile(
        "mma.sync.aligned.m16n8k16.row.col.f32.bf16.bf16.f32 "
        "{%0,%1,%2,%3}, {%4,%5,%6,%7}, {%8,%9}, {%0,%1,%2,%3};"
        : "+f"(c[0]), "+f"(c[1]), "+f"(c[2]), "+f"(c[3])
        : "r"(a[0]), "r"(a[1]), "r"(a[2]), "r"(a[3]), "r"(b0), "r"(b1));
}

__device__ __forceinline__ float gelu_exact(float t) {
    return 0.5f * t * (1.0f + erff(t * 0.70710678118654752f));
}

// C[M,N] = act(A[M,K] @ B[K,N] + bias); B supplied split+transposed bf16 [n][k].
__device__ __forceinline__ void gemm_body(
    const float* __restrict__ A,
    const __nv_bfloat16* __restrict__ BThi,
    const __nv_bfloat16* __restrict__ BTlo,
    const float* __restrict__ bias,
    float* __restrict__ C,
    int M, int N, int K, int act, int rowTile, int colTile)
{
    __shared__ __nv_bfloat16 sAhi[128][40];
    __shared__ __nv_bfloat16 sAlo[128][40];
    __shared__ __nv_bfloat16 sBhi[128][40];
    __shared__ __nv_bfloat16 sBlo[128][40];

    const int tid  = threadIdx.x;
    const int lane = tid & 31;
    const int wid  = tid >> 5;
    const int warpM = wid & 3;        // 4 warps over M (32 rows each)
    const int warpN = wid >> 2;       // 2 warps over N (64 cols each)
    const int rowBase = rowTile * 128;
    const int colBase = colTile * 128;

    float acc[2][8][4];
    #pragma unroll
    for (int mi = 0; mi < 2; ++mi)
        #pragma unroll
        for (int ni = 0; ni < 8; ++ni)
            #pragma unroll
            for (int q = 0; q < 4; ++q) acc[mi][ni][q] = 0.f;

    for (int k0 = 0; k0 < K; k0 += 32) {
        // A tile 128x32 fp32 -> split bf16
        #pragma unroll
        for (int t = 0; t < 4; ++t) {
            int s = tid + t * 256;          // 1024 float4 slots
            int m = s >> 3, kq = s & 7;
            int gr = rowBase + m;
            float4 v = (gr < M) ? *(const float4*)&A[(size_t)gr * K + k0 + kq * 4]
                                : make_float4(0.f, 0.f, 0.f, 0.f);
            __nv_bfloat162 h01 = __floats2bfloat162_rn(v.x, v.y);
            __nv_bfloat162 h23 = __floats2bfloat162_rn(v.z, v.w);
            float2 hf01 = __bfloat1622float2(h01);
            float2 hf23 = __bfloat1622float2(h23);
            __nv_bfloat162 l01 = __floats2bfloat162_rn(v.x - hf01.x, v.y - hf01.y);
            __nv_bfloat162 l23 = __floats2bfloat162_rn(v.z - hf23.x, v.w - hf23.y);
            *(__nv_bfloat162*)&sAhi[m][kq * 4]     = h01;
            *(__nv_bfloat162*)&sAhi[m][kq * 4 + 2] = h23;
            *(__nv_bfloat162*)&sAlo[m][kq * 4]     = l01;
            *(__nv_bfloat162*)&sAlo[m][kq * 4 + 2] = l23;
        }
        // B tile 128n x 32k bf16 (already [n][k])
        #pragma unroll
        for (int t = 0; t < 8; ++t) {
            int s = tid + t * 256;          // 2048 u32 slots
            int n = s >> 4, kw = s & 15;
            size_t gi = (size_t)(colBase + n) * K + k0 + kw * 2;
            *(__nv_bfloat162*)&sBhi[n][kw * 2] = *(const __nv_bfloat162*)&BThi[gi];
            *(__nv_bfloat162*)&sBlo[n][kw * 2] = *(const __nv_bfloat162*)&BTlo[gi];
        }
        __syncthreads();

        #pragma unroll
        for (int ks = 0; ks < 2; ++ks) {
            unsigned ah[2][4], al[2][4];
            #pragma unroll
            for (int mi = 0; mi < 2; ++mi) {
                int r0 = warpM * 32 + mi * 16 + (lane >> 2);
                int r1 = r0 + 8;
                int c0 = ks * 16 + (lane & 3) * 2;
                int c1 = c0 + 8;
                ah[mi][0] = *(const unsigned*)&sAhi[r0][c0];
                ah[mi][1] = *(const unsigned*)&sAhi[r1][c0];
                ah[mi][2] = *(const unsigned*)&sAhi[r0][c1];
                ah[mi][3] = *(const unsigned*)&sAhi[r1][c1];
                al[mi][0] = *(const unsigned*)&sAlo[r0][c0];
                al[mi][1] = *(const unsigned*)&sAlo[r1][c0];
                al[mi][2] = *(const unsigned*)&sAlo[r0][c1];
                al[mi][3] = *(const unsigned*)&sAlo[r1][c1];
            }
            #pragma unroll
            for (int ni = 0; ni < 8; ++ni) {
                int nr = warpN * 64 + ni * 8 + (lane >> 2);
                int c0 = ks * 16 + (lane & 3) * 2;
                unsigned bh0 = *(const unsigned*)&sBhi[nr][c0];
                unsigned bh1 = *(const unsigned*)&sBhi[nr][c0 + 8];
                unsigned bl0 = *(const unsigned*)&sBlo[nr][c0];
                unsigned bl1 = *(const unsigned*)&sBlo[nr][c0 + 8];
                #pragma unroll
                for (int mi = 0; mi < 2; ++mi) {
                    mma_bf16(acc[mi][ni], ah[mi], bh0, bh1);
                    mma_bf16(acc[mi][ni], ah[mi], bl0, bl1);
                    mma_bf16(acc[mi][ni], al[mi], bh0, bh1);
                }
            }
        }
        __syncthreads();
    }

    // epilogue
    #pragma unroll
    for (int mi = 0; mi < 2; ++mi) {
        int r0 = rowBase + warpM * 32 + mi * 16 + (lane >> 2);
        int r1 = r0 + 8;
        #pragma unroll
        for (int ni = 0; ni < 8; ++ni) {
            int c = colBase + warpN * 64 + ni * 8 + (lane & 3) * 2;
            float b0 = 0.f, b1v = 0.f;
            if (bias) { b0 = bias[c]; b1v = bias[c + 1]; }
            float x0 = acc[mi][ni][0] + b0, x1 = acc[mi][ni][1] + b1v;
            float x2 = acc[mi][ni][2] + b0, x3 = acc[mi][ni][3] + b1v;
            if (act) {
                x0 = gelu_exact(x0); x1 = gelu_exact(x1);
                x2 = gelu_exact(x2); x3 = gelu_exact(x3);
            }
            if (r0 < M) { float2 t0 = make_float2(x0, x1);
                          *(float2*)&C[(size_t)r0 * N + c] = t0; }
            if (r1 < M) { float2 t1 = make_float2(x2, x3);
                          *(float2*)&C[(size_t)r1 * N + c] = t1; }
        }
    }
}

__global__ __launch_bounds__(256) void k_gemm1(const float* __restrict__ x) {
    gemm_body(x, g_wThi + OFF_WG, g_wTlo + OFF_WG, nullptr, g_h,
              NN, DIM, DIM, 0, blockIdx.x, 0);
}
__global__ __launch_bounds__(256) void k_ffn1t(const float* __restrict__ h1,
                                               const float* __restrict__ b1) {
    gemm_body(h1, g_wThi + OFF_W1, g_wTlo + OFF_W1, b1, g_z,
              NN, HID, DIM, 1, blockIdx.x, blockIdx.y);
}
__global__ __launch_bounds__(256) void k_ffn2t(const float* __restrict__ b2) {
    gemm_body(g_z, g_wThi + OFF_W2, g_wTlo + OFF_W2, b2, g_h,
              NN, DIM, HID, 0, blockIdx.x, 0);
}

// ---------------- attention coefficients -------------------------------------
__global__ void k_attn(const float* __restrict__ att_s,
                       const float* __restrict__ att_d) {
    int idx = blockIdx.x * blockDim.x + threadIdx.x;
    if (idx >= NN * HEADS) return;
    int n = idx >> 3, hh = idx & 7;
    const float* hr = &g_h[(size_t)n * DIM + hh * 16];
    float s1 = 0.f, s2 = 0.f;
    #pragma unroll
    for (int k = 0; k < 16; ++k) {
        float hv = hr[k];
        s1 = fmaf(hv, att_s[hh * 16 + k], s1);
        s2 = fmaf(hv, att_d[hh * 16 + k], s2);
    }
    g_asrc[idx] = s1;
    g_adst[idx] = s2;
}

// ---------------- aggregation + residual + LN1 (1 warp / node) ---------------
__device__ __forceinline__ float leaky(float v) { return fmaxf(v, NEG * v); }

__global__ __launch_bounds__(256) void k_agg_ln(
    const float* __restrict__ x, const float* __restrict__ bg,
    const float* __restrict__ gamma, const float* __restrict__ beta,
    float* __restrict__ h1)
{
    int w = (blockIdx.x * blockDim.x + threadIdx.x) >> 5;
    if (w >= NN) return;
    const int lane = threadIdx.x & 31;

    float adst[8], asrci[8];
    {
        float4 a = *(const float4*)&g_adst[w * 8];
        float4 b = *(const float4*)&g_adst[w * 8 + 4];
        adst[0]=a.x; adst[1]=a.y; adst[2]=a.z; adst[3]=a.w;
        adst[4]=b.x; adst[5]=b.y; adst[6]=b.z; adst[7]=b.w;
        float4 c = *(const float4*)&g_asrc[w * 8];
        float4 d = *(const float4*)&g_asrc[w * 8 + 4];
        asrci[0]=c.x; asrci[1]=c.y; asrci[2]=c.z; asrci[3]=c.w;
        asrci[4]=d.x; asrci[5]=d.y; asrci[6]=d.z; asrci[7]=d.w;
    }

    const int beg = g_offsets[w];
    const int end = g_offsets[w + 1];

    float m[8];
    #pragma unroll
    for (int h = 0; h < 8; ++h) m[h] = leaky(asrci[h] + adst[h]);
    for (int j = beg + lane; j < end; j += 32) {
        int s = g_csr[j];
        float4 a = *(const float4*)&g_asrc[s * 8];
        float4 b = *(const float4*)&g_asrc[s * 8 + 4];
        m[0] = fmaxf(m[0], leaky(a.x + adst[0]));
        m[1] = fmaxf(m[1], leaky(a.y + adst[1]));
        m[2] = fmaxf(m[2], leaky(a.z + adst[2]));
        m[3] = fmaxf(m[3], leaky(a.w + adst[3]));
        m[4] = fmaxf(m[4], leaky(b.x + adst[4]));
        m[5] = fmaxf(m[5], leaky(b.y + adst[5]));
        m[6] = fmaxf(m[6], leaky(b.z + adst[6]));
        m[7] = fmaxf(m[7], leaky(b.w + adst[7]));
    }
    #pragma unroll
    for (int h = 0; h < 8; ++h)
        #pragma unroll
        for (int o = 16; o > 0; o >>= 1)
            m[h] = fmaxf(m[h], __shfl_xor_sync(0xFFFFFFFFu, m[h], o));

    const int myh = lane >> 2;
    float mm = m[0], adm = adst[0], asm_ = asrci[0];
    #pragma unroll
    for (int h = 1; h < 8; ++h)
        if (myh == h) { mm = m[h]; adm = adst[h]; asm_ = asrci[h]; }

    float l = 0.f;
    float4 acc = make_float4(0.f, 0.f, 0.f, 0.f);
    {
        float p = __expf(leaky(asm_ + adm) - mm);
        l += p;
        float4 hv = *(const float4*)&g_h[(size_t)w * DIM + lane * 4];
        acc.x += p * hv.x; acc.y += p * hv.y; acc.z += p * hv.z; acc.w += p * hv.w;
    }
    for (int j = beg; j < end; ++j) {
        int s = g_csr[j];
        float p = __expf(leaky(g_asrc[s * 8 + myh] + adm) - mm);
        l += p;
        float4 hv = *(const float4*)&g_h[(size_t)s * DIM + lane * 4];
        acc.x += p * hv.x; acc.y += p * hv.y; acc.z += p * hv.z; acc.w += p * hv.w;
    }
    float inv = 1.f / (l + 1e-16f);

    float4 xv  = *(const float4*)&x[(size_t)w * DIM + lane * 4];
    float4 bgv = *(const float4*)&bg[lane * 4];
    float4 v;
    v.x = xv.x + acc.x * inv + bgv.x;
    v.y = xv.y + acc.y * inv + bgv.y;
    v.z = xv.z + acc.z * inv + bgv.z;
    v.w = xv.w + acc.w * inv + bgv.w;

    float s = v.x + v.y + v.z + v.w;
    #pragma unroll
    for (int o = 16; o > 0; o >>= 1) s += __shfl_xor_sync(0xFFFFFFFFu, s, o);
    float mu = s * (1.f / DIM);
    v.x -= mu; v.y -= mu; v.z -= mu; v.w -= mu;
    float q = v.x * v.x + v.y * v.y + v.z * v.z + v.w * v.w;
    #pragma unroll
    for (int o = 16; o > 0; o >>= 1) q += __shfl_xor_sync(0xFFFFFFFFu, q, o);
    float rs = rsqrtf(q * (1.f / DIM) + LNEPS);
    float4 g  = *(const float4*)&gamma[lane * 4];
    float4 be = *(const float4*)&beta[lane * 4];
    float4 o4;
    o4.x = g.x * v.x * rs + be.x;
    o4.y = g.y * v.y * rs + be.y;
    o4.z = g.z * v.z * rs + be.z;
    o4.w = g.w * v.w * rs + be.w;
    *(float4*)&h1[(size_t)w * DIM + lane * 4] = o4;
}

// ---------------- final residual + LN2 (reads g_h = ffn out) ------------------
__global__ __launch_bounds__(256) void k_add_ln_fin(
    const float* __restrict__ gamma, const float* __restrict__ beta,
    float* __restrict__ io)
{
    int r = (blockIdx.x * blockDim.x + threadIdx.x) >> 5;
    if (r >= NN) return;
    const int lane = threadIdx.x & 31;
    const size_t base = (size_t)r * DIM + lane * 4;

    float4 a = *(const float4*)&io[base];
    float4 b = *(const float4*)&g_h[base];
    float4 v = make_float4(a.x + b.x, a.y + b.y, a.z + b.z, a.w + b.w);
    float s = v.x + v.y + v.z + v.w;
    #pragma unroll
    for (int o = 16; o > 0; o >>= 1) s += __shfl_xor_sync(0xFFFFFFFFu, s, o);
    float mu = s * (1.f / DIM);
    v.x -= mu; v.y -= mu; v.z -= mu; v.w -= mu;
    float q = v.x * v.x + v.y * v.y + v.z * v.z + v.w * v.w;
    #pragma unroll
    for (int o = 16; o > 0; o >>= 1) q += __shfl_xor_sync(0xFFFFFFFFu, q, o);
    float rs = rsqrtf(q * (1.f / DIM) + LNEPS);
    float4 g  = *(const float4*)&gamma[lane * 4];
    float4 be = *(const float4*)&beta[lane * 4];
    float4 o4;
    o4.x = g.x * v.x * rs + be.x;
    o4.y = g.y * v.y * rs + be.y;
    o4.z = g.z * v.z * rs + be.z;
    o4.w = g.w * v.w * rs + be.w;
    *(float4*)&io[base] = o4;
}

// ---------------- launcher (kernel launches ONLY) ----------------------------
extern "C" void kernel_launch(void* const* d_in, const int* in_sizes, int n_in,
                              void* d_out, int out_size)
{
    const float* x     = (const float*)d_in[0];
    const void*  ei    = d_in[1];
    const float* Wg    = (const float*)d_in[2];
    const float* att_s = (const float*)d_in[3];
    const float* att_d = (const float*)d_in[4];
    const float* bg    = (const float*)d_in[5];
    const float* gamma = (const float*)d_in[6];
    const float* beta  = (const float*)d_in[7];
    const float* W1    = (const float*)d_in[8];
    const float* b1    = (const float*)d_in[9];
    const float* W2    = (const float*)d_in[10];
    const float* b2    = (const float*)d_in[11];
    float*       out   = (float*)d_out;

    // dtype detection + CSR build (parallel scan)
    k_detect<<<1, 32>>>((const unsigned int*)ei);
    k_zero_int<<<(NN + 255) / 256, 256>>>();
    k_hist<<<(NE + 255) / 256, 256>>>(ei);
    k_scan_part<<<SCAN_NB, 1024>>>();
    k_scan_tops<<<1, 128>>>();
    k_scan_add<<<SCAN_NB, 1024>>>();
    k_scatter<<<(NE + 255) / 256, 256>>>(ei);

    // weight split+transpose
    k_convT<<<(DIM * DIM + 255) / 256, 256>>>(Wg, DIM, DIM, OFF_WG);
    k_convT<<<(DIM * HID + 255) / 256, 256>>>(W1, DIM, HID, OFF_W1);
    k_convT<<<(HID * DIM + 255) / 256, 256>>>(W2, HID, DIM, OFF_W2);

    // h = x @ W_gat  (tensor, bf16x3)
    k_gemm1<<<GB_ROWS, 256>>>(x);
    // attention coefficients
    k_attn<<<(NN * HEADS + 255) / 256, 256>>>(att_s, att_d);
    // h1 = LN(x + GAT_agg + b_gat) -> d_out
    k_agg_ln<<<(NN * 32 + 255) / 256, 256>>>(x, bg, gamma, beta, out);
    // z = gelu(h1 @ W1 + b1)
    k_ffn1t<<<dim3(GB_ROWS, HID / 128), 256>>>(out, b1);
    // ffn = z @ W2 + b2 -> g_h
    k_ffn2t<<<GB_ROWS, 256>>>(b2);
    // out = LN(h1 + ffn)
    k_add_ln_fin<<<(NN * 32 + 255) / 256, 256>>>(gamma, beta, out);
}

// round 6
// speedup vs baseline: 2.1696x; 1.3338x over previous
#include <cuda_runtime.h>
#include <cuda_fp16.h>
#include <math.h>

#define NN    100000
#define DIM   128
#define HEADS 8
#define NE    1600000
#define NEG   0.2f
#define LNEPS 1e-5f
#define HID   512
#define GB_ROWS 782            // ceil(NN/128)
#define SCAN_NB 98             // ceil(NN/1024)

#define OFF_WG 0
#define OFF_W1 16384           // 128*128
#define OFF_W2 81920           // + 128*512
#define WTOT   147456          // + 512*128

// ---------------- scratch (static device globals; no allocation) -------------
__device__ float  g_h   [(size_t)NN * DIM];   // x@Wg, later FFN2 out
__device__ __half g_z   [(size_t)NN * HID];   // FFN hidden (fp16)
__device__ float  g_asrc[NN * HEADS];
__device__ float  g_adst[NN * HEADS];
__device__ __half g_wThi[WTOT];               // W^T hi  [n][k]
__device__ __half g_wTlo[WTOT];               // W^T lo  [n][k]
__device__ int    g_counts  [NN];
__device__ int    g_cursors [NN];
__device__ int    g_offsets [NN + 1];
__device__ int    g_csr     [NE];
__device__ int    g_blocksum[SCAN_NB];
__device__ int    g_blockoff[SCAN_NB];
__device__ int    g_is64;

// ---------------- edge dtype detection ---------------------------------------
__global__ void k_detect(const unsigned int* __restrict__ ew) {
    if (threadIdx.x == 0 && blockIdx.x == 0) {
        unsigned int acc = 0;
        #pragma unroll
        for (int i = 0; i < 16; ++i) acc |= ew[2 * i + 1];
        g_is64 = (acc == 0) ? 1 : 0;
    }
}

// ---------------- CSR build --------------------------------------------------
__global__ void k_zero_int() {
    int i = blockIdx.x * blockDim.x + threadIdx.x;
    if (i < NN) { g_counts[i] = 0; g_cursors[i] = 0; }
}

__device__ __forceinline__ int edge_at(const void* ei, int is64, size_t idx) {
    if (is64) return (int)((const long long*)ei)[idx];
    return ((const int*)ei)[idx];
}

__global__ void k_hist(const void* __restrict__ ei) {
    int i = blockIdx.x * blockDim.x + threadIdx.x;
    if (i >= NE) return;
    int dst = edge_at(ei, g_is64, (size_t)NE + i);
    if ((unsigned)dst < (unsigned)NN) atomicAdd(&g_counts[dst], 1);
}

__global__ __launch_bounds__(1024) void k_scan_part() {
    __shared__ int ws[32];
    int tid = threadIdx.x;
    int i = blockIdx.x * 1024 + tid;
    int v = (i < NN) ? g_counts[i] : 0;
    int lane = tid & 31, wid = tid >> 5;
    int x = v;
    #pragma unroll
    for (int o = 1; o < 32; o <<= 1) {
        int y = __shfl_up_sync(0xFFFFFFFFu, x, o);
        if (lane >= o) x += y;
    }
    if (lane == 31) ws[wid] = x;
    __syncthreads();
    if (wid == 0) {
        int s = ws[lane];
        #pragma unroll
        for (int o = 1; o < 32; o <<= 1) {
            int y = __shfl_up_sync(0xFFFFFFFFu, s, o);
            if (lane >= o) s += y;
        }
        ws[lane] = s;
    }
    __syncthreads();
    int base = wid ? ws[wid - 1] : 0;
    int incl = base + x;
    if (i < NN) g_offsets[i] = incl - v;
    if (tid == 1023) g_blocksum[blockIdx.x] = incl;
}

__global__ void k_scan_tops() {
    __shared__ int ws[4];
    int t = threadIdx.x;
    int v = (t < SCAN_NB) ? g_blocksum[t] : 0;
    int lane = t & 31, wid = t >> 5;
    int x = v;
    #pragma unroll
    for (int o = 1; o < 32; o <<= 1) {
        int y = __shfl_up_sync(0xFFFFFFFFu, x, o);
        if (lane >= o) x += y;
    }
    if (lane == 31) ws[wid] = x;
    __syncthreads();
    int add = 0;
    for (int w = 0; w < wid; ++w) add += ws[w];
    x += add;
    if (t < SCAN_NB) g_blockoff[t] = x - v;
    if (t == SCAN_NB - 1) g_offsets[NN] = x;
}

__global__ __launch_bounds__(1024) void k_scan_add() {
    int i = blockIdx.x * 1024 + threadIdx.x;
    if (i < NN) g_offsets[i] += g_blockoff[blockIdx.x];
}

__global__ void k_scatter(const void* __restrict__ ei) {
    int i = blockIdx.x * blockDim.x + threadIdx.x;
    if (i >= NE) return;
    int src = edge_at(ei, g_is64, i);
    int dst = edge_at(ei, g_is64, (size_t)NE + i);
    if ((unsigned)src < (unsigned)NN && (unsigned)dst < (unsigned)NN) {
        int pos = g_offsets[dst] + atomicAdd(&g_cursors[dst], 1);
        g_csr[pos] = src;
    }
}

// -------- weight convert + transpose (fp32 [k][n] -> fp16 split [n][k]) ------
__global__ void k_convT(const float* __restrict__ src, int K, int N, int off) {
    int i = blockIdx.x * blockDim.x + threadIdx.x;
    if (i >= K * N) return;
    int k = i / N, n = i % N;
    float v = src[i];
    __half h = __float2half_rn(v);
    __half l = __float2half_rn(v - __half2float(h));
    g_wThi[off + n * K + k] = h;
    g_wTlo[off + n * K + k] = l;
}

// ---------------- fp16x2 tensor-core GEMM body --------------------------------
__device__ __forceinline__ void mma_f16(float* c, const unsigned* a,
                                        unsigned b0, unsigned b1) {
    asm volatile(
        "mma.sync.aligned.m16n8k16.row.col.f32.f16.f16.f32 "
        "{%0,%1,%2,%3}, {%4,%5,%6,%7}, {%8,%9}, {%0,%1,%2,%3};"
        : "+f"(c[0]), "+f"(c[1]), "+f"(c[2]), "+f"(c[3])
        : "r"(a[0]), "r"(a[1]), "r"(a[2]), "r"(a[3]), "r"(b0), "r"(b1));
}

__device__ __forceinline__ float gelu_exact(float t) {
    return 0.5f * t * (1.0f + erff(t * 0.70710678118654752f));
}

// C = act(A @ B + bias). B pre-split fp16 [n][k]. A fp32 or fp16 (template).
// Output to Cf (fp32) or Ch (fp16), whichever is non-null.
template<bool A_HALF>
__device__ __forceinline__ void gemm_body(
    const void* __restrict__ Ap,
    const __half* __restrict__ BThi,
    const __half* __restrict__ BTlo,
    const float* __restrict__ bias,
    float* __restrict__ Cf, __half* __restrict__ Ch,
    int M, int N, int K, int act, int rowTile, int colTile)
{
    __shared__ __half sA [128][40];
    __shared__ __half sBh[128][40];
    __shared__ __half sBl[128][40];

    const int tid  = threadIdx.x;
    const int lane = tid & 31;
    const int wid  = tid >> 5;
    const int warpM = wid & 3;
    const int warpN = wid >> 2;
    const int rowBase = rowTile * 128;
    const int colBase = colTile * 128;

    float acc[2][8][4];
    #pragma unroll
    for (int mi = 0; mi < 2; ++mi)
        #pragma unroll
        for (int ni = 0; ni < 8; ++ni)
            #pragma unroll
            for (int q = 0; q < 4; ++q) acc[mi][ni][q] = 0.f;

    for (int k0 = 0; k0 < K; k0 += 32) {
        // ---- A tile 128x32 -> fp16 hi
        if (A_HALF) {
            const __half* A = (const __half*)Ap;
            #pragma unroll
            for (int t = 0; t < 2; ++t) {
                int s = tid + t * 256;          // 512 slots of 8 halfs
                int m = s >> 2, ko = (s & 3) * 8;
                int gr = rowBase + m;
                uint4 v = (gr < M) ? *(const uint4*)&A[(size_t)gr * K + k0 + ko]
                                   : make_uint4(0, 0, 0, 0);
                *(uint4*)&sA[m][ko] = v;
            }
        } else {
            const float* A = (const float*)Ap;
            #pragma unroll
            for (int t = 0; t < 4; ++t) {
                int s = tid + t * 256;          // 1024 slots of float4
                int m = s >> 3, kq = s & 7;
                int gr = rowBase + m;
                float4 v = (gr < M) ? *(const float4*)&A[(size_t)gr * K + k0 + kq * 4]
                                    : make_float4(0.f, 0.f, 0.f, 0.f);
                __half2 h01 = __floats2half2_rn(v.x, v.y);
                __half2 h23 = __floats2half2_rn(v.z, v.w);
                *(__half2*)&sA[m][kq * 4]     = h01;
                *(__half2*)&sA[m][kq * 4 + 2] = h23;
            }
        }
        // ---- B tiles (fp16 hi / lo, already [n][k])
        #pragma unroll
        for (int t = 0; t < 2; ++t) {
            int s = tid + t * 256;              // 512 slots of 8 halfs
            int n = s >> 2, ko = (s & 3) * 8;
            size_t gi = (size_t)(colBase + n) * K + k0 + ko;
            *(uint4*)&sBh[n][ko] = *(const uint4*)&BThi[gi];
            *(uint4*)&sBl[n][ko] = *(const uint4*)&BTlo[gi];
        }
        __syncthreads();

        #pragma unroll
        for (int ks = 0; ks < 2; ++ks) {
            unsigned ah[2][4];
            #pragma unroll
            for (int mi = 0; mi < 2; ++mi) {
                int r0 = warpM * 32 + mi * 16 + (lane >> 2);
                int r1 = r0 + 8;
                int c0 = ks * 16 + (lane & 3) * 2;
                int c1 = c0 + 8;
                ah[mi][0] = *(const unsigned*)&sA[r0][c0];
                ah[mi][1] = *(const unsigned*)&sA[r1][c0];
                ah[mi][2] = *(const unsigned*)&sA[r0][c1];
                ah[mi][3] = *(const unsigned*)&sA[r1][c1];
            }
            #pragma unroll
            for (int ni = 0; ni < 8; ++ni) {
                int nr = warpN * 64 + ni * 8 + (lane >> 2);
                int c0 = ks * 16 + (lane & 3) * 2;
                unsigned bh0 = *(const unsigned*)&sBh[nr][c0];
                unsigned bh1 = *(const unsigned*)&sBh[nr][c0 + 8];
                unsigned bl0 = *(const unsigned*)&sBl[nr][c0];
                unsigned bl1 = *(const unsigned*)&sBl[nr][c0 + 8];
                #pragma unroll
                for (int mi = 0; mi < 2; ++mi) {
                    mma_f16(acc[mi][ni], ah[mi], bh0, bh1);
                    mma_f16(acc[mi][ni], ah[mi], bl0, bl1);
                }
            }
        }
        __syncthreads();
    }

    // epilogue
    #pragma unroll
    for (int mi = 0; mi < 2; ++mi) {
        int r0 = rowBase + warpM * 32 + mi * 16 + (lane >> 2);
        int r1 = r0 + 8;
        #pragma unroll
        for (int ni = 0; ni < 8; ++ni) {
            int c = colBase + warpN * 64 + ni * 8 + (lane & 3) * 2;
            float b0 = 0.f, b1v = 0.f;
            if (bias) { b0 = bias[c]; b1v = bias[c + 1]; }
            float x0 = acc[mi][ni][0] + b0, x1 = acc[mi][ni][1] + b1v;
            float x2 = acc[mi][ni][2] + b0, x3 = acc[mi][ni][3] + b1v;
            if (act) {
                x0 = gelu_exact(x0); x1 = gelu_exact(x1);
                x2 = gelu_exact(x2); x3 = gelu_exact(x3);
            }
            if (Ch) {
                if (r0 < M) *(__half2*)&Ch[(size_t)r0 * N + c] = __floats2half2_rn(x0, x1);
                if (r1 < M) *(__half2*)&Ch[(size_t)r1 * N + c] = __floats2half2_rn(x2, x3);
            } else {
                if (r0 < M) *(float2*)&Cf[(size_t)r0 * N + c] = make_float2(x0, x1);
                if (r1 < M) *(float2*)&Cf[(size_t)r1 * N + c] = make_float2(x2, x3);
            }
        }
    }
}

__global__ __launch_bounds__(256) void k_gemm1(const float* __restrict__ x) {
    gemm_body<false>(x, g_wThi + OFF_WG, g_wTlo + OFF_WG, nullptr,
                     g_h, nullptr, NN, DIM, DIM, 0, blockIdx.x, 0);
}
__global__ __launch_bounds__(256) void k_ffn1t(const float* __restrict__ h1,
                                               const float* __restrict__ b1) {
    gemm_body<false>(h1, g_wThi + OFF_W1, g_wTlo + OFF_W1, b1,
                     nullptr, g_z, NN, HID, DIM, 1, blockIdx.x, blockIdx.y);
}
__global__ __launch_bounds__(256) void k_ffn2t(const float* __restrict__ b2) {
    gemm_body<true>(g_z, g_wThi + OFF_W2, g_wTlo + OFF_W2, b2,
                    g_h, nullptr, NN, DIM, HID, 0, blockIdx.x, 0);
}

// ---------------- attention coefficients -------------------------------------
__global__ void k_attn(const float* __restrict__ att_s,
                       const float* __restrict__ att_d) {
    int idx = blockIdx.x * blockDim.x + threadIdx.x;
    if (idx >= NN * HEADS) return;
    int n = idx >> 3, hh = idx & 7;
    const float* hr = &g_h[(size_t)n * DIM + hh * 16];
    float s1 = 0.f, s2 = 0.f;
    #pragma unroll
    for (int k = 0; k < 16; ++k) {
        float hv = hr[k];
        s1 = fmaf(hv, att_s[hh * 16 + k], s1);
        s2 = fmaf(hv, att_d[hh * 16 + k], s2);
    }
    g_asrc[idx] = s1;
    g_adst[idx] = s2;
}

// -------- single-pass aggregation (no max; softmax shift-invariant) + LN1 ----
__device__ __forceinline__ float leaky(float v) { return fmaxf(v, NEG * v); }

__global__ __launch_bounds__(256) void k_agg_ln(
    const float* __restrict__ x, const float* __restrict__ bg,
    const float* __restrict__ gamma, const float* __restrict__ beta,
    float* __restrict__ h1)
{
    int w = (blockIdx.x * blockDim.x + threadIdx.x) >> 5;
    if (w >= NN) return;
    const int lane = threadIdx.x & 31;
    const int myh = lane >> 2;

    // per-lane head scalars (heads packed 8 contiguous floats)
    const float adm  = g_adst[w * 8 + myh];
    const float asm_ = g_asrc[w * 8 + myh];

    const int beg = g_offsets[w];
    const int end = g_offsets[w + 1];

    float l = 0.f;
    float4 acc = make_float4(0.f, 0.f, 0.f, 0.f);
    {   // self loop
        float p = __expf(leaky(asm_ + adm));
        l += p;
        float4 hv = *(const float4*)&g_h[(size_t)w * DIM + lane * 4];
        acc.x += p * hv.x; acc.y += p * hv.y; acc.z += p * hv.z; acc.w += p * hv.w;
    }
    for (int j = beg; j < end; ++j) {
        int s = g_csr[j];
        float p = __expf(leaky(g_asrc[s * 8 + myh] + adm));
        l += p;
        float4 hv = *(const float4*)&g_h[(size_t)s * DIM + lane * 4];
        acc.x += p * hv.x; acc.y += p * hv.y; acc.z += p * hv.z; acc.w += p * hv.w;
    }
    float inv = 1.f / (l + 1e-16f);

    float4 xv  = *(const float4*)&x[(size_t)w * DIM + lane * 4];
    float4 bgv = *(const float4*)&bg[lane * 4];
    float4 v;
    v.x = xv.x + acc.x * inv + bgv.x;
    v.y = xv.y + acc.y * inv + bgv.y;
    v.z = xv.z + acc.z * inv + bgv.z;
    v.w = xv.w + acc.w * inv + bgv.w;

    float s = v.x + v.y + v.z + v.w;
    #pragma unroll
    for (int o = 16; o > 0; o >>= 1) s += __shfl_xor_sync(0xFFFFFFFFu, s, o);
    float mu = s * (1.f / DIM);
    v.x -= mu; v.y -= mu; v.z -= mu; v.w -= mu;
    float q = v.x * v.x + v.y * v.y + v.z * v.z + v.w * v.w;
    #pragma unroll
    for (int o = 16; o > 0; o >>= 1) q += __shfl_xor_sync(0xFFFFFFFFu, q, o);
    float rs = rsqrtf(q * (1.f / DIM) + LNEPS);
    float4 g  = *(const float4*)&gamma[lane * 4];
    float4 be = *(const float4*)&beta[lane * 4];
    float4 o4;
    o4.x = g.x * v.x * rs + be.x;
    o4.y = g.y * v.y * rs + be.y;
    o4.z = g.z * v.z * rs + be.z;
    o4.w = g.w * v.w * rs + be.w;
    *(float4*)&h1[(size_t)w * DIM + lane * 4] = o4;
}

// ---------------- final residual + LN2 (reads g_h = ffn out) ------------------
__global__ __launch_bounds__(256) void k_add_ln_fin(
    const float* __restrict__ gamma, const float* __restrict__ beta,
    float* __restrict__ io)
{
    int r = (blockIdx.x * blockDim.x + threadIdx.x) >> 5;
    if (r >= NN) return;
    const int lane = threadIdx.x & 31;
    const size_t base = (size_t)r * DIM + lane * 4;

    float4 a = *(const float4*)&io[base];
    float4 b = *(const float4*)&g_h[base];
    float4 v = make_float4(a.x + b.x, a.y + b.y, a.z + b.z, a.w + b.w);
    float s = v.x + v.y + v.z + v.w;
    #pragma unroll
    for (int o = 16; o > 0; o >>= 1) s += __shfl_xor_sync(0xFFFFFFFFu, s, o);
    float mu = s * (1.f / DIM);
    v.x -= mu; v.y -= mu; v.z -= mu; v.w -= mu;
    float q = v.x * v.x + v.y * v.y + v.z * v.z + v.w * v.w;
    #pragma unroll
    for (int o = 16; o > 0; o >>= 1) q += __shfl_xor_sync(0xFFFFFFFFu, q, o);
    float rs = rsqrtf(q * (1.f / DIM) + LNEPS);
    float4 g  = *(const float4*)&gamma[lane * 4];
    float4 be = *(const float4*)&beta[lane * 4];
    float4 o4;
    o4.x = g.x * v.x * rs + be.x;
    o4.y = g.y * v.y * rs + be.y;
    o4.z = g.z * v.z * rs + be.z;
    o4.w = g.w * v.w * rs + be.w;
    *(float4*)&io[base] = o4;
}

// ---------------- launcher (kernel launches ONLY) ----------------------------
extern "C" void kernel_launch(void* const* d_in, const int* in_sizes, int n_in,
                              void* d_out, int out_size)
{
    const float* x     = (const float*)d_in[0];
    const void*  ei    = d_in[1];
    const float* Wg    = (const float*)d_in[2];
    const float* att_s = (const float*)d_in[3];
    const float* att_d = (const float*)d_in[4];
    const float* bg    = (const float*)d_in[5];
    const float* gamma = (const float*)d_in[6];
    const float* beta  = (const float*)d_in[7];
    const float* W1    = (const float*)d_in[8];
    const float* b1    = (const float*)d_in[9];
    const float* W2    = (const float*)d_in[10];
    const float* b2    = (const float*)d_in[11];
    float*       out   = (float*)d_out;

    // weight split first; launch #5 is k_gemm1 so ncu (-s 5) profiles the GEMM
    k_convT<<<(DIM * DIM + 255) / 256, 256>>>(Wg, DIM, DIM, OFF_WG);   // 0
    k_convT<<<(DIM * HID + 255) / 256, 256>>>(W1, DIM, HID, OFF_W1);   // 1
    k_convT<<<(HID * DIM + 255) / 256, 256>>>(W2, HID, DIM, OFF_W2);   // 2
    k_detect<<<1, 32>>>((const unsigned int*)ei);                      // 3
    k_zero_int<<<(NN + 255) / 256, 256>>>();                           // 4
    k_gemm1<<<GB_ROWS, 256>>>(x);                                      // 5 <- ncu
    k_hist<<<(NE + 255) / 256, 256>>>(ei);                             // 6
    k_scan_part<<<SCAN_NB, 1024>>>();
    k_scan_tops<<<1, 128>>>();
    k_scan_add<<<SCAN_NB, 1024>>>();
    k_scatter<<<(NE + 255) / 256, 256>>>(ei);
    k_attn<<<(NN * HEADS + 255) / 256, 256>>>(att_s, att_d);
    k_agg_ln<<<(NN * 32 + 255) / 256, 256>>>(x, bg, gamma, beta, out);
    k_ffn1t<<<dim3(GB_ROWS, HID / 128), 256>>>(out, b1);
    k_ffn2t<<<GB_ROWS, 256>>>(b2);
    k_add_ln_fin<<<(NN * 32 + 255) / 256, 256>>>(gamma, beta, out);
}

// round 8
// speedup vs baseline: 2.9938x; 1.3799x over previous
#include <cuda_runtime.h>
#include <cuda_fp16.h>
#include <math.h>

#define NN    100000
#define DIM   128
#define HEADS 8
#define NE    1600000
#define NEG   0.2f
#define LNEPS 1e-5f
#define HID   512
#define GB_ROWS 782            // ceil(NN/128)
#define SCAN_NB 98             // ceil(NN/1024)

#define OFF_WG 0
#define OFF_W1 16384           // 128*128
#define OFF_W2 81920           // + 128*512
#define WTOT   147456          // + 512*128

// ---------------- scratch (static device globals; no allocation) -------------
__device__ __half g_h16 [(size_t)NN * DIM];   // x@Wg (fp16)
__device__ float  g_ffn [(size_t)NN * DIM];   // FFN2 output (fp32)
__device__ __half g_z   [(size_t)NN * HID];   // FFN hidden (fp16)
__device__ float  g_asrc[NN * HEADS];
__device__ float  g_adst[NN * HEADS];
__device__ __half g_wT  [WTOT];               // W^T fp16 [n][k]
__device__ int    g_counts  [NN];
__device__ int    g_cursors [NN];
__device__ int    g_offsets [NN + 1];
__device__ int    g_csr     [NE];
__device__ int    g_blocksum[SCAN_NB];
__device__ int    g_blockoff[SCAN_NB];
__device__ int    g_is64;

// ---------------- edge dtype detection ---------------------------------------
__global__ void k_detect(const unsigned int* __restrict__ ew) {
    if (threadIdx.x == 0 && blockIdx.x == 0) {
        unsigned int acc = 0;
        #pragma unroll
        for (int i = 0; i < 16; ++i) acc |= ew[2 * i + 1];
        g_is64 = (acc == 0) ? 1 : 0;
    }
}

// ---------------- CSR build --------------------------------------------------
__global__ void k_zero_int() {
    int i = blockIdx.x * blockDim.x + threadIdx.x;
    if (i < NN) { g_counts[i] = 0; g_cursors[i] = 0; }
}

__device__ __forceinline__ int edge_at(const void* ei, int is64, size_t idx) {
    if (is64) return (int)((const long long*)ei)[idx];
    return ((const int*)ei)[idx];
}

__global__ void k_hist(const void* __restrict__ ei) {
    int i = blockIdx.x * blockDim.x + threadIdx.x;
    if (i >= NE) return;
    int dst = edge_at(ei, g_is64, (size_t)NE + i);
    if ((unsigned)dst < (unsigned)NN) atomicAdd(&g_counts[dst], 1);
}

__global__ __launch_bounds__(1024) void k_scan_part() {
    __shared__ int ws[32];
    int tid = threadIdx.x;
    int i = blockIdx.x * 1024 + tid;
    int v = (i < NN) ? g_counts[i] : 0;
    int lane = tid & 31, wid = tid >> 5;
    int x = v;
    #pragma unroll
    for (int o = 1; o < 32; o <<= 1) {
        int y = __shfl_up_sync(0xFFFFFFFFu, x, o);
        if (lane >= o) x += y;
    }
    if (lane == 31) ws[wid] = x;
    __syncthreads();
    if (wid == 0) {
        int s = ws[lane];
        #pragma unroll
        for (int o = 1; o < 32; o <<= 1) {
            int y = __shfl_up_sync(0xFFFFFFFFu, s, o);
            if (lane >= o) s += y;
        }
        ws[lane] = s;
    }
    __syncthreads();
    int base = wid ? ws[wid - 1] : 0;
    int incl = base + x;
    if (i < NN) g_offsets[i] = incl - v;
    if (tid == 1023) g_blocksum[blockIdx.x] = incl;
}

__global__ void k_scan_tops() {
    __shared__ int ws[4];
    int t = threadIdx.x;
    int v = (t < SCAN_NB) ? g_blocksum[t] : 0;
    int lane = t & 31, wid = t >> 5;
    int x = v;
    #pragma unroll
    for (int o = 1; o < 32; o <<= 1) {
        int y = __shfl_up_sync(0xFFFFFFFFu, x, o);
        if (lane >= o) x += y;
    }
    if (lane == 31) ws[wid] = x;
    __syncthreads();
    int add = 0;
    for (int w = 0; w < wid; ++w) add += ws[w];
    x += add;
    if (t < SCAN_NB) g_blockoff[t] = x - v;
    if (t == SCAN_NB - 1) g_offsets[NN] = x;
}

__global__ __launch_bounds__(1024) void k_scan_add() {
    int i = blockIdx.x * 1024 + threadIdx.x;
    if (i < NN) g_offsets[i] += g_blockoff[blockIdx.x];
}

__global__ void k_scatter(const void* __restrict__ ei) {
    int i = blockIdx.x * blockDim.x + threadIdx.x;
    if (i >= NE) return;
    int src = edge_at(ei, g_is64, i);
    int dst = edge_at(ei, g_is64, (size_t)NE + i);
    if ((unsigned)src < (unsigned)NN && (unsigned)dst < (unsigned)NN) {
        int pos = g_offsets[dst] + atomicAdd(&g_cursors[dst], 1);
        g_csr[pos] = src;
    }
}

// -------- weight convert + transpose (fp32 [k][n] -> fp16 [n][k]) ------------
__global__ void k_convT(const float* __restrict__ src, int K, int N, int off) {
    int i = blockIdx.x * blockDim.x + threadIdx.x;
    if (i >= K * N) return;
    int k = i / N, n = i % N;
    g_wT[off + n * K + k] = __float2half_rn(src[i]);
}

// ---------------- single fp16 tensor-core GEMM body ---------------------------
__device__ __forceinline__ void mma_f16(float* c, const unsigned* a,
                                        unsigned b0, unsigned b1) {
    asm volatile(
        "mma.sync.aligned.m16n8k16.row.col.f32.f16.f16.f32 "
        "{%0,%1,%2,%3}, {%4,%5,%6,%7}, {%8,%9}, {%0,%1,%2,%3};"
        : "+f"(c[0]), "+f"(c[1]), "+f"(c[2]), "+f"(c[3])
        : "r"(a[0]), "r"(a[1]), "r"(a[2]), "r"(a[3]), "r"(b0), "r"(b1));
}

__device__ __forceinline__ float gelu_exact(float t) {
    return 0.5f * t * (1.0f + erff(t * 0.70710678118654752f));
}

// C = act(A @ B + bias). B fp16 [n][k]. KC=64 chunks. 128x128 tile, 8 warps.
template<bool A_HALF, bool ACT, bool OUT_HALF>
__device__ __forceinline__ void gemm_body(
    const void* __restrict__ Ap,
    const __half* __restrict__ BT,
    const float* __restrict__ bias,
    float* __restrict__ Cf, __half* __restrict__ Ch,
    int M, int N, int K, int rowTile, int colTile)
{
    __shared__ __half sA[128][72];
    __shared__ __half sB[128][72];

    const int tid  = threadIdx.x;
    const int lane = tid & 31;
    const int wid  = tid >> 5;
    const int warpM = wid & 3;
    const int warpN = wid >> 2;
    const int rowBase = rowTile * 128;
    const int colBase = colTile * 128;

    float acc[2][8][4];
    #pragma unroll
    for (int mi = 0; mi < 2; ++mi)
        #pragma unroll
        for (int ni = 0; ni < 8; ++ni)
            #pragma unroll
            for (int q = 0; q < 4; ++q) acc[mi][ni][q] = 0.f;

    for (int k0 = 0; k0 < K; k0 += 64) {
        // ---- A tile 128x64
        if (A_HALF) {
            const __half* A = (const __half*)Ap;
            #pragma unroll
            for (int t = 0; t < 4; ++t) {
                int s = tid + t * 256;              // 1024 uint4
                int m = s >> 3, ko = (s & 7) * 8;
                int gr = rowBase + m;
                uint4 v = (gr < M) ? *(const uint4*)&A[(size_t)gr * K + k0 + ko]
                                   : make_uint4(0, 0, 0, 0);
                *(uint4*)&sA[m][ko] = v;
            }
        } else {
            const float* A = (const float*)Ap;
            #pragma unroll
            for (int t = 0; t < 8; ++t) {
                int s = tid + t * 256;              // 2048 float4
                int m = s >> 4, kq = s & 15;
                int gr = rowBase + m;
                float4 v = (gr < M) ? *(const float4*)&A[(size_t)gr * K + k0 + kq * 4]
                                    : make_float4(0.f, 0.f, 0.f, 0.f);
                *(__half2*)&sA[m][kq * 4]     = __floats2half2_rn(v.x, v.y);
                *(__half2*)&sA[m][kq * 4 + 2] = __floats2half2_rn(v.z, v.w);
            }
        }
        // ---- B tile 128n x 64k (fp16, already [n][k])
        #pragma unroll
        for (int t = 0; t < 4; ++t) {
            int s = tid + t * 256;                  // 1024 uint4
            int n = s >> 3, ko = (s & 7) * 8;
            *(uint4*)&sB[n][ko] =
                *(const uint4*)&BT[(size_t)(colBase + n) * K + k0 + ko];
        }
        __syncthreads();

        #pragma unroll
        for (int ks = 0; ks < 4; ++ks) {
            unsigned ah[2][4];
            #pragma unroll
            for (int mi = 0; mi < 2; ++mi) {
                int r0 = warpM * 32 + mi * 16 + (lane >> 2);
                int r1 = r0 + 8;
                int c0 = ks * 16 + (lane & 3) * 2;
                int c1 = c0 + 8;
                ah[mi][0] = *(const unsigned*)&sA[r0][c0];
                ah[mi][1] = *(const unsigned*)&sA[r1][c0];
                ah[mi][2] = *(const unsigned*)&sA[r0][c1];
                ah[mi][3] = *(const unsigned*)&sA[r1][c1];
            }
            #pragma unroll
            for (int ni = 0; ni < 8; ++ni) {
                int nr = warpN * 64 + ni * 8 + (lane >> 2);
                int c0 = ks * 16 + (lane & 3) * 2;
                unsigned b0 = *(const unsigned*)&sB[nr][c0];
                unsigned b1 = *(const unsigned*)&sB[nr][c0 + 8];
                mma_f16(acc[0][ni], ah[0], b0, b1);
                mma_f16(acc[1][ni], ah[1], b0, b1);
            }
        }
        __syncthreads();
    }

    #pragma unroll
    for (int mi = 0; mi < 2; ++mi) {
        int r0 = rowBase + warpM * 32 + mi * 16 + (lane >> 2);
        int r1 = r0 + 8;
        #pragma unroll
        for (int ni = 0; ni < 8; ++ni) {
            int c = colBase + warpN * 64 + ni * 8 + (lane & 3) * 2;
            float b0 = 0.f, b1v = 0.f;
            if (bias) { b0 = bias[c]; b1v = bias[c + 1]; }
            float x0 = acc[mi][ni][0] + b0, x1 = acc[mi][ni][1] + b1v;
            float x2 = acc[mi][ni][2] + b0, x3 = acc[mi][ni][3] + b1v;
            if (ACT) {
                x0 = gelu_exact(x0); x1 = gelu_exact(x1);
                x2 = gelu_exact(x2); x3 = gelu_exact(x3);
            }
            if (OUT_HALF) {
                if (r0 < M) *(__half2*)&Ch[(size_t)r0 * N + c] = __floats2half2_rn(x0, x1);
                if (r1 < M) *(__half2*)&Ch[(size_t)r1 * N + c] = __floats2half2_rn(x2, x3);
            } else {
                if (r0 < M) *(float2*)&Cf[(size_t)r0 * N + c] = make_float2(x0, x1);
                if (r1 < M) *(float2*)&Cf[(size_t)r1 * N + c] = make_float2(x2, x3);
            }
        }
    }
}

__global__ __launch_bounds__(256) void k_gemm1(const float* __restrict__ x) {
    gemm_body<false, false, true>(x, g_wT + OFF_WG, nullptr,
                                  nullptr, g_h16, NN, DIM, DIM, blockIdx.x, 0);
}
__global__ __launch_bounds__(256) void k_ffn1t(const float* __restrict__ h1,
                                               const float* __restrict__ b1) {
    gemm_body<false, true, true>(h1, g_wT + OFF_W1, b1,
                                 nullptr, g_z, NN, HID, DIM,
                                 blockIdx.x, blockIdx.y);
}
__global__ __launch_bounds__(256) void k_ffn2t(const float* __restrict__ b2) {
    gemm_body<true, false, false>(g_z, g_wT + OFF_W2, b2,
                                  g_ffn, nullptr, NN, DIM, HID, blockIdx.x, 0);
}

// ---------------- attention coefficients (fp16 h) -----------------------------
__global__ void k_attn(const float* __restrict__ att_s,
                       const float* __restrict__ att_d) {
    int idx = blockIdx.x * blockDim.x + threadIdx.x;
    if (idx >= NN * HEADS) return;
    int n = idx >> 3, hh = idx & 7;
    const __half* hr = &g_h16[(size_t)n * DIM + hh * 16];
    float s1 = 0.f, s2 = 0.f;
    #pragma unroll
    for (int k = 0; k < 8; ++k) {
        float2 hv = __half22float2(*(const __half2*)&hr[k * 2]);
        s1 = fmaf(hv.x, att_s[hh * 16 + k * 2],     s1);
        s1 = fmaf(hv.y, att_s[hh * 16 + k * 2 + 1], s1);
        s2 = fmaf(hv.x, att_d[hh * 16 + k * 2],     s2);
        s2 = fmaf(hv.y, att_d[hh * 16 + k * 2 + 1], s2);
    }
    g_asrc[idx] = s1;
    g_adst[idx] = s2;
}

// -------- single-pass aggregation + residual + LN1 (1 warp / node) -----------
// lane covers dims [4*lane, 4*lane+4)  (32 lanes x 4 = 128 ✓), head = lane>>2
__device__ __forceinline__ float leaky(float v) { return fmaxf(v, NEG * v); }

__global__ __launch_bounds__(256) void k_agg_ln(
    const float* __restrict__ x, const float* __restrict__ bg,
    const float* __restrict__ gamma, const float* __restrict__ beta,
    float* __restrict__ h1)
{
    int w = (blockIdx.x * blockDim.x + threadIdx.x) >> 5;
    if (w >= NN) return;
    const int lane = threadIdx.x & 31;
    const int myh = lane >> 2;

    const float adm  = g_adst[w * 8 + myh];
    const float asm_ = g_asrc[w * 8 + myh];

    const int beg = g_offsets[w];
    const int end = g_offsets[w + 1];

    float l = 0.f;
    float a0 = 0.f, a1 = 0.f, a2 = 0.f, a3 = 0.f;
    {   // self loop
        float p = __expf(leaky(asm_ + adm));
        l += p;
        uint2 u = *(const uint2*)&g_h16[(size_t)w * DIM + lane * 4];
        float2 h0 = __half22float2(*(__half2*)&u.x);
        float2 h1v = __half22float2(*(__half2*)&u.y);
        a0 += p * h0.x; a1 += p * h0.y; a2 += p * h1v.x; a3 += p * h1v.y;
    }
    for (int j = beg; j < end; ++j) {
        int s = g_csr[j];
        float p = __expf(leaky(g_asrc[s * 8 + myh] + adm));
        l += p;
        uint2 u = *(const uint2*)&g_h16[(size_t)s * DIM + lane * 4];
        float2 h0 = __half22float2(*(__half2*)&u.x);
        float2 h1v = __half22float2(*(__half2*)&u.y);
        a0 += p * h0.x; a1 += p * h0.y; a2 += p * h1v.x; a3 += p * h1v.y;
    }
    float inv = 1.f / (l + 1e-16f);

    float4 xv  = *(const float4*)&x[(size_t)w * DIM + lane * 4];
    float4 bgv = *(const float4*)&bg[lane * 4];
    float4 v;
    v.x = xv.x + a0 * inv + bgv.x;
    v.y = xv.y + a1 * inv + bgv.y;
    v.z = xv.z + a2 * inv + bgv.z;
    v.w = xv.w + a3 * inv + bgv.w;

    float s = v.x + v.y + v.z + v.w;
    #pragma unroll
    for (int o = 16; o > 0; o >>= 1) s += __shfl_xor_sync(0xFFFFFFFFu, s, o);
    float mu = s * (1.f / DIM);
    v.x -= mu; v.y -= mu; v.z -= mu; v.w -= mu;
    float q = v.x * v.x + v.y * v.y + v.z * v.z + v.w * v.w;
    #pragma unroll
    for (int o = 16; o > 0; o >>= 1) q += __shfl_xor_sync(0xFFFFFFFFu, q, o);
    float rs = rsqrtf(q * (1.f / DIM) + LNEPS);
    float4 g  = *(const float4*)&gamma[lane * 4];
    float4 be = *(const float4*)&beta[lane * 4];
    float4 o4;
    o4.x = g.x * v.x * rs + be.x;
    o4.y = g.y * v.y * rs + be.y;
    o4.z = g.z * v.z * rs + be.z;
    o4.w = g.w * v.w * rs + be.w;
    *(float4*)&h1[(size_t)w * DIM + lane * 4] = o4;
}

// ---------------- final residual + LN2 (reads g_ffn) --------------------------
__global__ __launch_bounds__(256) void k_add_ln_fin(
    const float* __restrict__ gamma, const float* __restrict__ beta,
    float* __restrict__ io)
{
    int r = (blockIdx.x * blockDim.x + threadIdx.x) >> 5;
    if (r >= NN) return;
    const int lane = threadIdx.x & 31;
    const size_t base = (size_t)r * DIM + lane * 4;

    float4 a = *(const float4*)&io[base];
    float4 b = *(const float4*)&g_ffn[base];
    float4 v = make_float4(a.x + b.x, a.y + b.y, a.z + b.z, a.w + b.w);
    float s = v.x + v.y + v.z + v.w;
    #pragma unroll
    for (int o = 16; o > 0; o >>= 1) s += __shfl_xor_sync(0xFFFFFFFFu, s, o);
    float mu = s * (1.f / DIM);
    v.x -= mu; v.y -= mu; v.z -= mu; v.w -= mu;
    float q = v.x * v.x + v.y * v.y + v.z * v.z + v.w * v.w;
    #pragma unroll
    for (int o = 16; o > 0; o >>= 1) q += __shfl_xor_sync(0xFFFFFFFFu, q, o);
    float rs = rsqrtf(q * (1.f / DIM) + LNEPS);
    float4 g  = *(const float4*)&gamma[lane * 4];
    float4 be = *(const float4*)&beta[lane * 4];
    float4 o4;
    o4.x = g.x * v.x * rs + be.x;
    o4.y = g.y * v.y * rs + be.y;
    o4.z = g.z * v.z * rs + be.z;
    o4.w = g.w * v.w * rs + be.w;
    *(float4*)&io[base] = o4;
}

// ---------------- launcher (kernel launches ONLY) ----------------------------
extern "C" void kernel_launch(void* const* d_in, const int* in_sizes, int n_in,
                              void* d_out, int out_size)
{
    const float* x     = (const float*)d_in[0];
    const void*  ei    = d_in[1];
    const float* Wg    = (const float*)d_in[2];
    const float* att_s = (const float*)d_in[3];
    const float* att_d = (const float*)d_in[4];
    const float* bg    = (const float*)d_in[5];
    const float* gamma = (const float*)d_in[6];
    const float* beta  = (const float*)d_in[7];
    const float* W1    = (const float*)d_in[8];
    const float* b1    = (const float*)d_in[9];
    const float* W2    = (const float*)d_in[10];
    const float* b2    = (const float*)d_in[11];
    float*       out   = (float*)d_out;

    k_convT<<<(DIM * DIM + 255) / 256, 256>>>(Wg, DIM, DIM, OFF_WG);
    k_convT<<<(DIM * HID + 255) / 256, 256>>>(W1, DIM, HID, OFF_W1);
    k_convT<<<(HID * DIM + 255) / 256, 256>>>(W2, HID, DIM, OFF_W2);
    k_detect<<<1, 32>>>((const unsigned int*)ei);
    k_zero_int<<<(NN + 255) / 256, 256>>>();
    k_gemm1<<<GB_ROWS, 256>>>(x);
    k_hist<<<(NE + 255) / 256, 256>>>(ei);
    k_scan_part<<<SCAN_NB, 1024>>>();
    k_scan_tops<<<1, 128>>>();
    k_scan_add<<<SCAN_NB, 1024>>>();
    k_scatter<<<(NE + 255) / 256, 256>>>(ei);
    k_attn<<<(NN * HEADS + 255) / 256, 256>>>(att_s, att_d);
    k_agg_ln<<<(NN * 32 + 255) / 256, 256>>>(x, bg, gamma, beta, out);
    k_ffn1t<<<dim3(GB_ROWS, HID / 128), 256>>>(out, b1);
    k_ffn2t<<<GB_ROWS, 256>>>(b2);
    k_add_ln_fin<<<(NN * 32 + 255) / 256, 256>>>(gamma, beta, out);
}

// round 9
// speedup vs baseline: 3.0315x; 1.0126x over previous
#include <cuda_runtime.h>
#include <cuda_fp16.h>
#include <math.h>

#define NN    100000
#define DIM   128
#define HEADS 8
#define NE    1600000
#define NEG   0.2f
#define LNEPS 1e-5f
#define HID   512
#define GB_ROWS 782            // ceil(NN/128)
#define SCAN_NB 98             // ceil(NN/1024)

#define OFF_WG 0
#define OFF_W1 16384           // 128*128
#define OFF_W2 81920           // + 128*512
#define WTOT   147456          // + 512*128

// ---------------- scratch (static device globals; no allocation) -------------
__device__ __half g_h16 [(size_t)NN * DIM];   // x@Wg (fp16)
__device__ __half g_z   [(size_t)NN * HID];   // FFN hidden (fp16)
__device__ float  g_asrc[NN * HEADS];
__device__ float  g_adst[NN * HEADS];
__device__ __half g_wT  [WTOT];               // W^T fp16 [n][k]
__device__ int    g_counts  [NN];
__device__ int    g_cursors [NN];
__device__ int    g_offsets [NN + 1];
__device__ int    g_csr     [NE];
__device__ int    g_blocksum[SCAN_NB];
__device__ int    g_blockoff[SCAN_NB];
__device__ int    g_is64;

// ---------------- edge dtype detection ---------------------------------------
__global__ void k_detect(const unsigned int* __restrict__ ew) {
    if (threadIdx.x == 0 && blockIdx.x == 0) {
        unsigned int acc = 0;
        #pragma unroll
        for (int i = 0; i < 16; ++i) acc |= ew[2 * i + 1];
        g_is64 = (acc == 0) ? 1 : 0;
    }
}

// ---------------- CSR build --------------------------------------------------
__global__ void k_zero_int() {
    int i = blockIdx.x * blockDim.x + threadIdx.x;
    if (i < NN) { g_counts[i] = 0; g_cursors[i] = 0; }
}

__device__ __forceinline__ int edge_at(const void* ei, int is64, size_t idx) {
    if (is64) return (int)((const long long*)ei)[idx];
    return ((const int*)ei)[idx];
}

__global__ void k_hist(const void* __restrict__ ei) {
    int i = blockIdx.x * blockDim.x + threadIdx.x;
    if (i >= NE) return;
    int dst = edge_at(ei, g_is64, (size_t)NE + i);
    if ((unsigned)dst < (unsigned)NN) atomicAdd(&g_counts[dst], 1);
}

__global__ __launch_bounds__(1024) void k_scan_part() {
    __shared__ int ws[32];
    int tid = threadIdx.x;
    int i = blockIdx.x * 1024 + tid;
    int v = (i < NN) ? g_counts[i] : 0;
    int lane = tid & 31, wid = tid >> 5;
    int x = v;
    #pragma unroll
    for (int o = 1; o < 32; o <<= 1) {
        int y = __shfl_up_sync(0xFFFFFFFFu, x, o);
        if (lane >= o) x += y;
    }
    if (lane == 31) ws[wid] = x;
    __syncthreads();
    if (wid == 0) {
        int s = ws[lane];
        #pragma unroll
        for (int o = 1; o < 32; o <<= 1) {
            int y = __shfl_up_sync(0xFFFFFFFFu, s, o);
            if (lane >= o) s += y;
        }
        ws[lane] = s;
    }
    __syncthreads();
    int base = wid ? ws[wid - 1] : 0;
    int incl = base + x;
    if (i < NN) g_offsets[i] = incl - v;
    if (tid == 1023) g_blocksum[blockIdx.x] = incl;
}

__global__ void k_scan_tops() {
    __shared__ int ws[4];
    int t = threadIdx.x;
    int v = (t < SCAN_NB) ? g_blocksum[t] : 0;
    int lane = t & 31, wid = t >> 5;
    int x = v;
    #pragma unroll
    for (int o = 1; o < 32; o <<= 1) {
        int y = __shfl_up_sync(0xFFFFFFFFu, x, o);
        if (lane >= o) x += y;
    }
    if (lane == 31) ws[wid] = x;
    __syncthreads();
    int add = 0;
    for (int w = 0; w < wid; ++w) add += ws[w];
    x += add;
    if (t < SCAN_NB) g_blockoff[t] = x - v;
    if (t == SCAN_NB - 1) g_offsets[NN] = x;
}

__global__ __launch_bounds__(1024) void k_scan_add() {
    int i = blockIdx.x * 1024 + threadIdx.x;
    if (i < NN) g_offsets[i] += g_blockoff[blockIdx.x];
}

__global__ void k_scatter(const void* __restrict__ ei) {
    int i = blockIdx.x * blockDim.x + threadIdx.x;
    if (i >= NE) return;
    int src = edge_at(ei, g_is64, i);
    int dst = edge_at(ei, g_is64, (size_t)NE + i);
    if ((unsigned)src < (unsigned)NN && (unsigned)dst < (unsigned)NN) {
        int pos = g_offsets[dst] + atomicAdd(&g_cursors[dst], 1);
        g_csr[pos] = src;
    }
}

// -------- weight convert + transpose (fp32 [k][n] -> fp16 [n][k]) ------------
__global__ void k_convT(const float* __restrict__ src, int K, int N, int off) {
    int i = blockIdx.x * blockDim.x + threadIdx.x;
    if (i >= K * N) return;
    int k = i / N, n = i % N;
    g_wT[off + n * K + k] = __float2half_rn(src[i]);
}

// ---------------- pipelined fp16 tensor-core GEMM ----------------------------
__device__ __forceinline__ void mma_f16(float* c, const unsigned* a,
                                        unsigned b0, unsigned b1) {
    asm volatile(
        "mma.sync.aligned.m16n8k16.row.col.f32.f16.f16.f32 "
        "{%0,%1,%2,%3}, {%4,%5,%6,%7}, {%8,%9}, {%0,%1,%2,%3};"
        : "+f"(c[0]), "+f"(c[1]), "+f"(c[2]), "+f"(c[3])
        : "r"(a[0]), "r"(a[1]), "r"(a[2]), "r"(a[3]), "r"(b0), "r"(b1));
}

__device__ __forceinline__ unsigned smem_u32(const void* p) {
    return (unsigned)__cvta_generic_to_shared(p);
}
__device__ __forceinline__ void cp16(unsigned dst, const void* src, int sz) {
    asm volatile("cp.async.cg.shared.global [%0], [%1], 16, %2;"
                 :: "r"(dst), "l"(src), "r"(sz));
}
__device__ __forceinline__ void cp_commit() {
    asm volatile("cp.async.commit_group;");
}
__device__ __forceinline__ void cp_wait0() {
    asm volatile("cp.async.wait_group 0;");
}

__device__ __forceinline__ float gelu_exact(float t) {
    return 0.5f * t * (1.0f + erff(t * 0.70710678118654752f));
}

// EPI: 0 = plain fp16 store; 1 = bias+gelu fp16 store; 2 = bias+residual+LN2
//      (fp32 io in/out, in-place).
template<bool A_HALF, int EPI>
__device__ __forceinline__ void gemm_body(
    const void* __restrict__ Ap,
    const __half* __restrict__ BT,
    const float* __restrict__ bias,
    __half* __restrict__ Ch,
    float* __restrict__ io,
    const float* __restrict__ gamma, const float* __restrict__ beta,
    int M, int N, int K, int rowTile, int colTile)
{
    __shared__ __half sA[2][128][40];
    __shared__ __half sB[2][128][40];
    __shared__ float  redS[2][128];
    __shared__ float  redQ[2][128];

    const int tid  = threadIdx.x;
    const int lane = tid & 31;
    const int wid  = tid >> 5;
    const int warpM = wid & 3;
    const int warpN = wid >> 2;
    const int rowBase = rowTile * 128;
    const int colBase = colTile * 128;
    const int nc = K >> 5;                   // KC = 32

    auto load_chunk = [&](int c, int st) {
        int k0 = c * 32;
        if (A_HALF) {
            const __half* A = (const __half*)Ap;
            #pragma unroll
            for (int t = 0; t < 2; ++t) {
                int s = tid + t * 256;              // 512 uint4
                int m = s >> 2, ko = (s & 3) * 8;
                int gr = rowBase + m;
                int ok = (gr < M);
                const void* gp = &A[(size_t)(ok ? gr : 0) * K + k0 + ko];
                cp16(smem_u32(&sA[st][m][ko]), gp, ok ? 16 : 0);
            }
        } else {
            const float* A = (const float*)Ap;
            #pragma unroll
            for (int t = 0; t < 4; ++t) {
                int s = tid + t * 256;              // 1024 float4
                int m = s >> 3, kq = s & 7;
                int gr = rowBase + m;
                float4 v = (gr < M) ? *(const float4*)&A[(size_t)gr * K + k0 + kq * 4]
                                    : make_float4(0.f, 0.f, 0.f, 0.f);
                *(__half2*)&sA[st][m][kq * 4]     = __floats2half2_rn(v.x, v.y);
                *(__half2*)&sA[st][m][kq * 4 + 2] = __floats2half2_rn(v.z, v.w);
            }
        }
        #pragma unroll
        for (int t = 0; t < 2; ++t) {
            int s = tid + t * 256;                  // 512 uint4
            int n = s >> 2, ko = (s & 3) * 8;
            cp16(smem_u32(&sB[st][n][ko]),
                 &BT[(size_t)(colBase + n) * K + k0 + ko], 16);
        }
        cp_commit();
    };

    float acc[2][8][4];
    #pragma unroll
    for (int mi = 0; mi < 2; ++mi)
        #pragma unroll
        for (int ni = 0; ni < 8; ++ni)
            #pragma unroll
            for (int q = 0; q < 4; ++q) acc[mi][ni][q] = 0.f;

    load_chunk(0, 0);
    for (int c = 0; c < nc; ++c) {
        cp_wait0();
        __syncthreads();
        if (c + 1 < nc) load_chunk(c + 1, (c + 1) & 1);
        const int st = c & 1;

        #pragma unroll
        for (int ks = 0; ks < 2; ++ks) {
            unsigned ah[2][4];
            #pragma unroll
            for (int mi = 0; mi < 2; ++mi) {
                int r0 = warpM * 32 + mi * 16 + (lane >> 2);
                int r1 = r0 + 8;
                int c0 = ks * 16 + (lane & 3) * 2;
                int c1 = c0 + 8;
                ah[mi][0] = *(const unsigned*)&sA[st][r0][c0];
                ah[mi][1] = *(const unsigned*)&sA[st][r1][c0];
                ah[mi][2] = *(const unsigned*)&sA[st][r0][c1];
                ah[mi][3] = *(const unsigned*)&sA[st][r1][c1];
            }
            #pragma unroll
            for (int ni = 0; ni < 8; ++ni) {
                int nr = warpN * 64 + ni * 8 + (lane >> 2);
                int c0 = ks * 16 + (lane & 3) * 2;
                unsigned b0 = *(const unsigned*)&sB[st][nr][c0];
                unsigned b1 = *(const unsigned*)&sB[st][nr][c0 + 8];
                mma_f16(acc[0][ni], ah[0], b0, b1);
                mma_f16(acc[1][ni], ah[1], b0, b1);
            }
        }
        __syncthreads();
    }

    if (EPI == 0 || EPI == 1) {
        #pragma unroll
        for (int mi = 0; mi < 2; ++mi) {
            int r0 = rowBase + warpM * 32 + mi * 16 + (lane >> 2);
            int r1 = r0 + 8;
            #pragma unroll
            for (int ni = 0; ni < 8; ++ni) {
                int c = colBase + warpN * 64 + ni * 8 + (lane & 3) * 2;
                float b0 = 0.f, b1v = 0.f;
                if (EPI == 1) { b0 = bias[c]; b1v = bias[c + 1]; }
                float x0 = acc[mi][ni][0] + b0, x1 = acc[mi][ni][1] + b1v;
                float x2 = acc[mi][ni][2] + b0, x3 = acc[mi][ni][3] + b1v;
                if (EPI == 1) {
                    x0 = gelu_exact(x0); x1 = gelu_exact(x1);
                    x2 = gelu_exact(x2); x3 = gelu_exact(x3);
                }
                if (r0 < M) *(__half2*)&Ch[(size_t)r0 * N + c] = __floats2half2_rn(x0, x1);
                if (r1 < M) *(__half2*)&Ch[(size_t)r1 * N + c] = __floats2half2_rn(x2, x3);
            }
        }
    } else {
        // EPI 2: v = acc + bias + io; LN over row; io = gamma*(v-mu)*rs + beta
        float sS[2][2] = {{0.f, 0.f}, {0.f, 0.f}};
        float sQ[2][2] = {{0.f, 0.f}, {0.f, 0.f}};
        #pragma unroll
        for (int mi = 0; mi < 2; ++mi) {
            int r0 = rowBase + warpM * 32 + mi * 16 + (lane >> 2);
            int r1 = r0 + 8;
            #pragma unroll
            for (int ni = 0; ni < 8; ++ni) {
                int c = warpN * 64 + ni * 8 + (lane & 3) * 2;
                float b0 = bias[c], b1v = bias[c + 1];
                float2 i0 = (r0 < M) ? *(const float2*)&io[(size_t)r0 * N + c]
                                     : make_float2(0.f, 0.f);
                float2 i1 = (r1 < M) ? *(const float2*)&io[(size_t)r1 * N + c]
                                     : make_float2(0.f, 0.f);
                float v0 = acc[mi][ni][0] + b0 + i0.x;
                float v1 = acc[mi][ni][1] + b1v + i0.y;
                float v2 = acc[mi][ni][2] + b0 + i1.x;
                float v3 = acc[mi][ni][3] + b1v + i1.y;
                acc[mi][ni][0] = v0; acc[mi][ni][1] = v1;
                acc[mi][ni][2] = v2; acc[mi][ni][3] = v3;
                sS[mi][0] += v0 + v1;       sS[mi][1] += v2 + v3;
                sQ[mi][0] += v0*v0 + v1*v1; sQ[mi][1] += v2*v2 + v3*v3;
            }
        }
        #pragma unroll
        for (int mi = 0; mi < 2; ++mi)
            #pragma unroll
            for (int k = 0; k < 2; ++k)
                #pragma unroll
                for (int o = 1; o < 4; o <<= 1) {
                    sS[mi][k] += __shfl_xor_sync(0xFFFFFFFFu, sS[mi][k], o);
                    sQ[mi][k] += __shfl_xor_sync(0xFFFFFFFFu, sQ[mi][k], o);
                }
        if ((lane & 3) == 0) {
            #pragma unroll
            for (int mi = 0; mi < 2; ++mi) {
                int lr = warpM * 32 + mi * 16 + (lane >> 2);
                redS[warpN][lr]     = sS[mi][0];
                redS[warpN][lr + 8] = sS[mi][1];
                redQ[warpN][lr]     = sQ[mi][0];
                redQ[warpN][lr + 8] = sQ[mi][1];
            }
        }
        __syncthreads();
        #pragma unroll
        for (int mi = 0; mi < 2; ++mi) {
            int lr0 = warpM * 32 + mi * 16 + (lane >> 2);
            int lr1 = lr0 + 8;
            float S0 = redS[0][lr0] + redS[1][lr0];
            float S1 = redS[0][lr1] + redS[1][lr1];
            float Q0 = redQ[0][lr0] + redQ[1][lr0];
            float Q1 = redQ[0][lr1] + redQ[1][lr1];
            float mu0 = S0 * (1.f / DIM), mu1 = S1 * (1.f / DIM);
            float rs0 = rsqrtf(fmaxf(Q0 * (1.f / DIM) - mu0 * mu0, 0.f) + LNEPS);
            float rs1 = rsqrtf(fmaxf(Q1 * (1.f / DIM) - mu1 * mu1, 0.f) + LNEPS);
            int r0 = rowBase + lr0;
            int r1 = rowBase + lr1;
            #pragma unroll
            for (int ni = 0; ni < 8; ++ni) {
                int c = warpN * 64 + ni * 8 + (lane & 3) * 2;
                float2 gv = *(const float2*)&gamma[c];
                float2 bv = *(const float2*)&beta[c];
                if (r0 < M) {
                    float2 o0;
                    o0.x = gv.x * (acc[mi][ni][0] - mu0) * rs0 + bv.x;
                    o0.y = gv.y * (acc[mi][ni][1] - mu0) * rs0 + bv.y;
                    *(float2*)&io[(size_t)r0 * N + c] = o0;
                }
                if (r1 < M) {
                    float2 o1;
                    o1.x = gv.x * (acc[mi][ni][2] - mu1) * rs1 + bv.x;
                    o1.y = gv.y * (acc[mi][ni][3] - mu1) * rs1 + bv.y;
                    *(float2*)&io[(size_t)r1 * N + c] = o1;
                }
            }
        }
    }
}

__global__ __launch_bounds__(256) void k_gemm1(const float* __restrict__ x) {
    gemm_body<false, 0>(x, g_wT + OFF_WG, nullptr, g_h16, nullptr,
                        nullptr, nullptr, NN, DIM, DIM, blockIdx.x, 0);
}
__global__ __launch_bounds__(256) void k_ffn1t(const float* __restrict__ h1,
                                               const float* __restrict__ b1) {
    gemm_body<false, 1>(h1, g_wT + OFF_W1, b1, g_z, nullptr,
                        nullptr, nullptr, NN, HID, DIM, blockIdx.x, blockIdx.y);
}
__global__ __launch_bounds__(256) void k_ffn2t(const float* __restrict__ b2,
                                               const float* __restrict__ gamma,
                                               const float* __restrict__ beta,
                                               float* __restrict__ io) {
    gemm_body<true, 2>(g_z, g_wT + OFF_W2, b2, nullptr, io,
                       gamma, beta, NN, DIM, HID, blockIdx.x, 0);
}

// ---------------- attention coefficients (fp16 h) -----------------------------
__global__ void k_attn(const float* __restrict__ att_s,
                       const float* __restrict__ att_d) {
    int idx = blockIdx.x * blockDim.x + threadIdx.x;
    if (idx >= NN * HEADS) return;
    int n = idx >> 3, hh = idx & 7;
    const __half* hr = &g_h16[(size_t)n * DIM + hh * 16];
    float s1 = 0.f, s2 = 0.f;
    #pragma unroll
    for (int k = 0; k < 8; ++k) {
        float2 hv = __half22float2(*(const __half2*)&hr[k * 2]);
        s1 = fmaf(hv.x, att_s[hh * 16 + k * 2],     s1);
        s1 = fmaf(hv.y, att_s[hh * 16 + k * 2 + 1], s1);
        s2 = fmaf(hv.x, att_d[hh * 16 + k * 2],     s2);
        s2 = fmaf(hv.y, att_d[hh * 16 + k * 2 + 1], s2);
    }
    g_asrc[idx] = s1;
    g_adst[idx] = s2;
}

// -------- single-pass aggregation + residual + LN1 (1 warp / node) -----------
__device__ __forceinline__ float leaky(float v) { return fmaxf(v, NEG * v); }

__global__ __launch_bounds__(256) void k_agg_ln(
    const float* __restrict__ x, const float* __restrict__ bg,
    const float* __restrict__ gamma, const float* __restrict__ beta,
    float* __restrict__ h1)
{
    int w = (blockIdx.x * blockDim.x + threadIdx.x) >> 5;
    if (w >= NN) return;
    const int lane = threadIdx.x & 31;
    const int myh = lane >> 2;

    const float adm  = g_adst[w * 8 + myh];
    const float asm_ = g_asrc[w * 8 + myh];

    const int beg = g_offsets[w];
    const int end = g_offsets[w + 1];

    float l = 0.f;
    float a0 = 0.f, a1 = 0.f, a2 = 0.f, a3 = 0.f;
    {   // self loop
        float p = __expf(leaky(asm_ + adm));
        l += p;
        uint2 u = *(const uint2*)&g_h16[(size_t)w * DIM + lane * 4];
        float2 h0 = __half22float2(*(__half2*)&u.x);
        float2 h1v = __half22float2(*(__half2*)&u.y);
        a0 += p * h0.x; a1 += p * h0.y; a2 += p * h1v.x; a3 += p * h1v.y;
    }
    int j = beg;
    for (; j + 1 < end; j += 2) {
        int s0 = g_csr[j];
        int s1 = g_csr[j + 1];
        float p0 = __expf(leaky(g_asrc[s0 * 8 + myh] + adm));
        float p1 = __expf(leaky(g_asrc[s1 * 8 + myh] + adm));
        uint2 u0 = *(const uint2*)&g_h16[(size_t)s0 * DIM + lane * 4];
        uint2 u1 = *(const uint2*)&g_h16[(size_t)s1 * DIM + lane * 4];
        l += p0 + p1;
        float2 q0 = __half22float2(*(__half2*)&u0.x);
        float2 q1 = __half22float2(*(__half2*)&u0.y);
        float2 r0 = __half22float2(*(__half2*)&u1.x);
        float2 r1 = __half22float2(*(__half2*)&u1.y);
        a0 += p0 * q0.x + p1 * r0.x;
        a1 += p0 * q0.y + p1 * r0.y;
        a2 += p0 * q1.x + p1 * r1.x;
        a3 += p0 * q1.y + p1 * r1.y;
    }
    if (j < end) {
        int s = g_csr[j];
        float p = __expf(leaky(g_asrc[s * 8 + myh] + adm));
        l += p;
        uint2 u = *(const uint2*)&g_h16[(size_t)s * DIM + lane * 4];
        float2 h0 = __half22float2(*(__half2*)&u.x);
        float2 h1v = __half22float2(*(__half2*)&u.y);
        a0 += p * h0.x; a1 += p * h0.y; a2 += p * h1v.x; a3 += p * h1v.y;
    }
    float inv = 1.f / (l + 1e-16f);

    float4 xv  = *(const float4*)&x[(size_t)w * DIM + lane * 4];
    float4 bgv = *(const float4*)&bg[lane * 4];
    float4 v;
    v.x = xv.x + a0 * inv + bgv.x;
    v.y = xv.y + a1 * inv + bgv.y;
    v.z = xv.z + a2 * inv + bgv.z;
    v.w = xv.w + a3 * inv + bgv.w;

    float s = v.x + v.y + v.z + v.w;
    #pragma unroll
    for (int o = 16; o > 0; o >>= 1) s += __shfl_xor_sync(0xFFFFFFFFu, s, o);
    float mu = s * (1.f / DIM);
    v.x -= mu; v.y -= mu; v.z -= mu; v.w -= mu;
    float q = v.x * v.x + v.y * v.y + v.z * v.z + v.w * v.w;
    #pragma unroll
    for (int o = 16; o > 0; o >>= 1) q += __shfl_xor_sync(0xFFFFFFFFu, q, o);
    float rs = rsqrtf(q * (1.f / DIM) + LNEPS);
    float4 g  = *(const float4*)&gamma[lane * 4];
    float4 be = *(const float4*)&beta[lane * 4];
    float4 o4;
    o4.x = g.x * v.x * rs + be.x;
    o4.y = g.y * v.y * rs + be.y;
    o4.z = g.z * v.z * rs + be.z;
    o4.w = g.w * v.w * rs + be.w;
    *(float4*)&h1[(size_t)w * DIM + lane * 4] = o4;
}

// ---------------- launcher (kernel launches ONLY) ----------------------------
extern "C" void kernel_launch(void* const* d_in, const int* in_sizes, int n_in,
                              void* d_out, int out_size)
{
    const float* x     = (const float*)d_in[0];
    const void*  ei    = d_in[1];
    const float* Wg    = (const float*)d_in[2];
    const float* att_s = (const float*)d_in[3];
    const float* att_d = (const float*)d_in[4];
    const float* bg    = (const float*)d_in[5];
    const float* gamma = (const float*)d_in[6];
    const float* beta  = (const float*)d_in[7];
    const float* W1    = (const float*)d_in[8];
    const float* b1    = (const float*)d_in[9];
    const float* W2    = (const float*)d_in[10];
    const float* b2    = (const float*)d_in[11];
    float*       out   = (float*)d_out;

    k_convT<<<(DIM * DIM + 255) / 256, 256>>>(Wg, DIM, DIM, OFF_WG);
    k_convT<<<(DIM * HID + 255) / 256, 256>>>(W1, DIM, HID, OFF_W1);
    k_convT<<<(HID * DIM + 255) / 256, 256>>>(W2, HID, DIM, OFF_W2);
    k_detect<<<1, 32>>>((const unsigned int*)ei);
    k_zero_int<<<(NN + 255) / 256, 256>>>();
    k_gemm1<<<GB_ROWS, 256>>>(x);
    k_hist<<<(NE + 255) / 256, 256>>>(ei);
    k_scan_part<<<SCAN_NB, 1024>>>();
    k_scan_tops<<<1, 128>>>();
    k_scan_add<<<SCAN_NB, 1024>>>();
    k_scatter<<<(NE + 255) / 256, 256>>>(ei);
    k_attn<<<(NN * HEADS + 255) / 256, 256>>>(att_s, att_d);
    k_agg_ln<<<(NN * 32 + 255) / 256, 256>>>(x, bg, gamma, beta, out);
    k_ffn1t<<<dim3(GB_ROWS, HID / 128), 256>>>(out, b1);
    k_ffn2t<<<GB_ROWS, 256>>>(b2, gamma, beta, out);
}

// round 10
// speedup vs baseline: 3.1831x; 1.0500x over previous
#include <cuda_runtime.h>
#include <cuda_fp16.h>
#include <math.h>

#define NN    100000
#define DIM   128
#define HEADS 8
#define NE    1600000
#define NEG   0.2f
#define LNEPS 1e-5f
#define HID   512
#define GB_ROWS 782            // ceil(NN/128)
#define SCAN_NB 98             // ceil(NN/1024)

#define OFF_WG 0
#define OFF_W1 16384           // 128*128
#define OFF_W2 81920           // + 128*512
#define WTOT   147456          // + 512*128

// ---------------- scratch (static device globals; no allocation) -------------
__device__ __half g_h16 [(size_t)NN * DIM];   // x@Wg (fp16)
__device__ __half g_z   [(size_t)NN * HID];   // FFN hidden (fp16)
__device__ float  g_asrc[NN * HEADS];
__device__ float  g_adst[NN * HEADS];
__device__ __half g_wT  [WTOT];               // W^T fp16 [n][k]
__device__ int    g_counts  [NN];
__device__ int    g_cursors [NN];
__device__ int    g_offsets [NN + 1];
__device__ int    g_csr     [NE];
__device__ int    g_blocksum[SCAN_NB];
__device__ int    g_blockoff[SCAN_NB];
__device__ int    g_is64;

// ---------------- prep: zero counters + edge dtype detection ------------------
__global__ void k_prep(const unsigned int* __restrict__ ew) {
    int i = blockIdx.x * blockDim.x + threadIdx.x;
    if (i < NN) { g_counts[i] = 0; g_cursors[i] = 0; }
    if (i == 0) {
        unsigned int acc = 0;
        #pragma unroll
        for (int t = 0; t < 16; ++t) acc |= ew[2 * t + 1];
        g_is64 = (acc == 0) ? 1 : 0;
    }
}

__device__ __forceinline__ int edge_at(const void* ei, int is64, size_t idx) {
    if (is64) return (int)((const long long*)ei)[idx];
    return ((const int*)ei)[idx];
}

__global__ void k_hist(const void* __restrict__ ei) {
    int i = blockIdx.x * blockDim.x + threadIdx.x;
    if (i >= NE) return;
    int dst = edge_at(ei, g_is64, (size_t)NE + i);
    if ((unsigned)dst < (unsigned)NN) atomicAdd(&g_counts[dst], 1);
}

__global__ __launch_bounds__(1024) void k_scan_part() {
    __shared__ int ws[32];
    int tid = threadIdx.x;
    int i = blockIdx.x * 1024 + tid;
    int v = (i < NN) ? g_counts[i] : 0;
    int lane = tid & 31, wid = tid >> 5;
    int x = v;
    #pragma unroll
    for (int o = 1; o < 32; o <<= 1) {
        int y = __shfl_up_sync(0xFFFFFFFFu, x, o);
        if (lane >= o) x += y;
    }
    if (lane == 31) ws[wid] = x;
    __syncthreads();
    if (wid == 0) {
        int s = ws[lane];
        #pragma unroll
        for (int o = 1; o < 32; o <<= 1) {
            int y = __shfl_up_sync(0xFFFFFFFFu, s, o);
            if (lane >= o) s += y;
        }
        ws[lane] = s;
    }
    __syncthreads();
    int base = wid ? ws[wid - 1] : 0;
    int incl = base + x;
    if (i < NN) g_offsets[i] = incl - v;
    if (tid == 1023) g_blocksum[blockIdx.x] = incl;
}

__global__ void k_scan_tops() {
    __shared__ int ws[4];
    int t = threadIdx.x;
    int v = (t < SCAN_NB) ? g_blocksum[t] : 0;
    int lane = t & 31, wid = t >> 5;
    int x = v;
    #pragma unroll
    for (int o = 1; o < 32; o <<= 1) {
        int y = __shfl_up_sync(0xFFFFFFFFu, x, o);
        if (lane >= o) x += y;
    }
    if (lane == 31) ws[wid] = x;
    __syncthreads();
    int add = 0;
    for (int w = 0; w < wid; ++w) add += ws[w];
    x += add;
    if (t < SCAN_NB) g_blockoff[t] = x - v;
    if (t == SCAN_NB - 1) g_offsets[NN] = x;
}

__global__ __launch_bounds__(1024) void k_scan_add() {
    int i = blockIdx.x * 1024 + threadIdx.x;
    if (i < NN) g_offsets[i] += g_blockoff[blockIdx.x];
}

__global__ void k_scatter(const void* __restrict__ ei) {
    int i = blockIdx.x * blockDim.x + threadIdx.x;
    if (i >= NE) return;
    int src = edge_at(ei, g_is64, i);
    int dst = edge_at(ei, g_is64, (size_t)NE + i);
    if ((unsigned)src < (unsigned)NN && (unsigned)dst < (unsigned)NN) {
        int pos = g_offsets[dst] + atomicAdd(&g_cursors[dst], 1);
        g_csr[pos] = src;
    }
}

// -------- all-weights convert+transpose (fp32 [k][n] -> fp16 [n][k]) ----------
__global__ void k_convT_all(const float* __restrict__ Wg,
                            const float* __restrict__ W1,
                            const float* __restrict__ W2) {
    int i = blockIdx.x * blockDim.x + threadIdx.x;
    if (i >= WTOT) return;
    const float* src; int K, N, off, loc;
    if (i < OFF_W1)      { src = Wg; K = DIM; N = DIM; off = OFF_WG; loc = i; }
    else if (i < OFF_W2) { src = W1; K = DIM; N = HID; off = OFF_W1; loc = i - OFF_W1; }
    else                 { src = W2; K = HID; N = DIM; off = OFF_W2; loc = i - OFF_W2; }
    int k = loc / N, n = loc % N;
    g_wT[off + n * K + k] = __float2half_rn(src[loc]);
}

// ---------------- pipelined fp16 tensor-core GEMM ----------------------------
__device__ __forceinline__ void mma_f16(float* c, const unsigned* a,
                                        unsigned b0, unsigned b1) {
    asm volatile(
        "mma.sync.aligned.m16n8k16.row.col.f32.f16.f16.f32 "
        "{%0,%1,%2,%3}, {%4,%5,%6,%7}, {%8,%9}, {%0,%1,%2,%3};"
        : "+f"(c[0]), "+f"(c[1]), "+f"(c[2]), "+f"(c[3])
        : "r"(a[0]), "r"(a[1]), "r"(a[2]), "r"(a[3]), "r"(b0), "r"(b1));
}

__device__ __forceinline__ unsigned smem_u32(const void* p) {
    return (unsigned)__cvta_generic_to_shared(p);
}
__device__ __forceinline__ void cp16(unsigned dst, const void* src, int sz) {
    asm volatile("cp.async.cg.shared.global [%0], [%1], 16, %2;"
                 :: "r"(dst), "l"(src), "r"(sz));
}
__device__ __forceinline__ void cp_commit() {
    asm volatile("cp.async.commit_group;");
}
__device__ __forceinline__ void cp_wait0() {
    asm volatile("cp.async.wait_group 0;");
}

__device__ __forceinline__ float gelu_exact(float t) {
    return 0.5f * t * (1.0f + erff(t * 0.70710678118654752f));
}

// EPI: 0 = plain fp16 store; 1 = bias+gelu fp16 store; 2 = bias+residual+LN2
template<bool A_HALF, int EPI>
__device__ __forceinline__ void gemm_body(
    const void* __restrict__ Ap,
    const __half* __restrict__ BT,
    const float* __restrict__ bias,
    __half* __restrict__ Ch,
    float* __restrict__ io,
    const float* __restrict__ gamma, const float* __restrict__ beta,
    int M, int N, int K, int rowTile, int colTile)
{
    __shared__ __half sA[2][128][40];
    __shared__ __half sB[2][128][40];
    __shared__ float  redS[2][128];
    __shared__ float  redQ[2][128];

    const int tid  = threadIdx.x;
    const int lane = tid & 31;
    const int wid  = tid >> 5;
    const int warpM = wid & 3;
    const int warpN = wid >> 2;
    const int rowBase = rowTile * 128;
    const int colBase = colTile * 128;
    const int nc = K >> 5;                   // KC = 32

    auto load_chunk = [&](int c, int st) {
        int k0 = c * 32;
        if (A_HALF) {
            const __half* A = (const __half*)Ap;
            #pragma unroll
            for (int t = 0; t < 2; ++t) {
                int s = tid + t * 256;
                int m = s >> 2, ko = (s & 3) * 8;
                int gr = rowBase + m;
                int ok = (gr < M);
                const void* gp = &A[(size_t)(ok ? gr : 0) * K + k0 + ko];
                cp16(smem_u32(&sA[st][m][ko]), gp, ok ? 16 : 0);
            }
        } else {
            const float* A = (const float*)Ap;
            #pragma unroll
            for (int t = 0; t < 4; ++t) {
                int s = tid + t * 256;
                int m = s >> 3, kq = s & 7;
                int gr = rowBase + m;
                float4 v = (gr < M) ? *(const float4*)&A[(size_t)gr * K + k0 + kq * 4]
                                    : make_float4(0.f, 0.f, 0.f, 0.f);
                *(__half2*)&sA[st][m][kq * 4]     = __floats2half2_rn(v.x, v.y);
                *(__half2*)&sA[st][m][kq * 4 + 2] = __floats2half2_rn(v.z, v.w);
            }
        }
        #pragma unroll
        for (int t = 0; t < 2; ++t) {
            int s = tid + t * 256;
            int n = s >> 2, ko = (s & 3) * 8;
            cp16(smem_u32(&sB[st][n][ko]),
                 &BT[(size_t)(colBase + n) * K + k0 + ko], 16);
        }
        cp_commit();
    };

    float acc[2][8][4];
    #pragma unroll
    for (int mi = 0; mi < 2; ++mi)
        #pragma unroll
        for (int ni = 0; ni < 8; ++ni)
            #pragma unroll
            for (int q = 0; q < 4; ++q) acc[mi][ni][q] = 0.f;

    load_chunk(0, 0);
    for (int c = 0; c < nc; ++c) {
        cp_wait0();
        __syncthreads();
        if (c + 1 < nc) load_chunk(c + 1, (c + 1) & 1);
        const int st = c & 1;

        #pragma unroll
        for (int ks = 0; ks < 2; ++ks) {
            unsigned ah[2][4];
            #pragma unroll
            for (int mi = 0; mi < 2; ++mi) {
                int r0 = warpM * 32 + mi * 16 + (lane >> 2);
                int r1 = r0 + 8;
                int c0 = ks * 16 + (lane & 3) * 2;
                int c1 = c0 + 8;
                ah[mi][0] = *(const unsigned*)&sA[st][r0][c0];
                ah[mi][1] = *(const unsigned*)&sA[st][r1][c0];
                ah[mi][2] = *(const unsigned*)&sA[st][r0][c1];
                ah[mi][3] = *(const unsigned*)&sA[st][r1][c1];
            }
            #pragma unroll
            for (int ni = 0; ni < 8; ++ni) {
                int nr = warpN * 64 + ni * 8 + (lane >> 2);
                int c0 = ks * 16 + (lane & 3) * 2;
                unsigned b0 = *(const unsigned*)&sB[st][nr][c0];
                unsigned b1 = *(const unsigned*)&sB[st][nr][c0 + 8];
                mma_f16(acc[0][ni], ah[0], b0, b1);
                mma_f16(acc[1][ni], ah[1], b0, b1);
            }
        }
        __syncthreads();
    }

    if (EPI == 0 || EPI == 1) {
        #pragma unroll
        for (int mi = 0; mi < 2; ++mi) {
            int r0 = rowBase + warpM * 32 + mi * 16 + (lane >> 2);
            int r1 = r0 + 8;
            #pragma unroll
            for (int ni = 0; ni < 8; ++ni) {
                int c = colBase + warpN * 64 + ni * 8 + (lane & 3) * 2;
                float b0 = 0.f, b1v = 0.f;
                if (EPI == 1) { b0 = bias[c]; b1v = bias[c + 1]; }
                float x0 = acc[mi][ni][0] + b0, x1 = acc[mi][ni][1] + b1v;
                float x2 = acc[mi][ni][2] + b0, x3 = acc[mi][ni][3] + b1v;
                if (EPI == 1) {
                    x0 = gelu_exact(x0); x1 = gelu_exact(x1);
                    x2 = gelu_exact(x2); x3 = gelu_exact(x3);
                }
                if (r0 < M) *(__half2*)&Ch[(size_t)r0 * N + c] = __floats2half2_rn(x0, x1);
                if (r1 < M) *(__half2*)&Ch[(size_t)r1 * N + c] = __floats2half2_rn(x2, x3);
            }
        }
    } else {
        float sS[2][2] = {{0.f, 0.f}, {0.f, 0.f}};
        float sQ[2][2] = {{0.f, 0.f}, {0.f, 0.f}};
        #pragma unroll
        for (int mi = 0; mi < 2; ++mi) {
            int r0 = rowBase + warpM * 32 + mi * 16 + (lane >> 2);
            int r1 = r0 + 8;
            #pragma unroll
            for (int ni = 0; ni < 8; ++ni) {
                int c = warpN * 64 + ni * 8 + (lane & 3) * 2;
                float b0 = bias[c], b1v = bias[c + 1];
                float2 i0 = (r0 < M) ? *(const float2*)&io[(size_t)r0 * N + c]
                                     : make_float2(0.f, 0.f);
                float2 i1 = (r1 < M) ? *(const float2*)&io[(size_t)r1 * N + c]
                                     : make_float2(0.f, 0.f);
                float v0 = acc[mi][ni][0] + b0 + i0.x;
                float v1 = acc[mi][ni][1] + b1v + i0.y;
                float v2 = acc[mi][ni][2] + b0 + i1.x;
                float v3 = acc[mi][ni][3] + b1v + i1.y;
                acc[mi][ni][0] = v0; acc[mi][ni][1] = v1;
                acc[mi][ni][2] = v2; acc[mi][ni][3] = v3;
                sS[mi][0] += v0 + v1;       sS[mi][1] += v2 + v3;
                sQ[mi][0] += v0*v0 + v1*v1; sQ[mi][1] += v2*v2 + v3*v3;
            }
        }
        #pragma unroll
        for (int mi = 0; mi < 2; ++mi)
            #pragma unroll
            for (int k = 0; k < 2; ++k)
                #pragma unroll
                for (int o = 1; o < 4; o <<= 1) {
                    sS[mi][k] += __shfl_xor_sync(0xFFFFFFFFu, sS[mi][k], o);
                    sQ[mi][k] += __shfl_xor_sync(0xFFFFFFFFu, sQ[mi][k], o);
                }
        if ((lane & 3) == 0) {
            #pragma unroll
            for (int mi = 0; mi < 2; ++mi) {
                int lr = warpM * 32 + mi * 16 + (lane >> 2);
                redS[warpN][lr]     = sS[mi][0];
                redS[warpN][lr + 8] = sS[mi][1];
                redQ[warpN][lr]     = sQ[mi][0];
                redQ[warpN][lr + 8] = sQ[mi][1];
            }
        }
        __syncthreads();
        #pragma unroll
        for (int mi = 0; mi < 2; ++mi) {
            int lr0 = warpM * 32 + mi * 16 + (lane >> 2);
            int lr1 = lr0 + 8;
            float S0 = redS[0][lr0] + redS[1][lr0];
            float S1 = redS[0][lr1] + redS[1][lr1];
            float Q0 = redQ[0][lr0] + redQ[1][lr0];
            float Q1 = redQ[0][lr1] + redQ[1][lr1];
            float mu0 = S0 * (1.f / DIM), mu1 = S1 * (1.f / DIM);
            float rs0 = rsqrtf(fmaxf(Q0 * (1.f / DIM) - mu0 * mu0, 0.f) + LNEPS);
            float rs1 = rsqrtf(fmaxf(Q1 * (1.f / DIM) - mu1 * mu1, 0.f) + LNEPS);
            int r0 = rowBase + lr0;
            int r1 = rowBase + lr1;
            #pragma unroll
            for (int ni = 0; ni < 8; ++ni) {
                int c = warpN * 64 + ni * 8 + (lane & 3) * 2;
                float2 gv = *(const float2*)&gamma[c];
                float2 bv = *(const float2*)&beta[c];
                if (r0 < M) {
                    float2 o0;
                    o0.x = gv.x * (acc[mi][ni][0] - mu0) * rs0 + bv.x;
                    o0.y = gv.y * (acc[mi][ni][1] - mu0) * rs0 + bv.y;
                    *(float2*)&io[(size_t)r0 * N + c] = o0;
                }
                if (r1 < M) {
                    float2 o1;
                    o1.x = gv.x * (acc[mi][ni][2] - mu1) * rs1 + bv.x;
                    o1.y = gv.y * (acc[mi][ni][3] - mu1) * rs1 + bv.y;
                    *(float2*)&io[(size_t)r1 * N + c] = o1;
                }
            }
        }
    }
}

__global__ __launch_bounds__(256) void k_gemm1(const float* __restrict__ x) {
    gemm_body<false, 0>(x, g_wT + OFF_WG, nullptr, g_h16, nullptr,
                        nullptr, nullptr, NN, DIM, DIM, blockIdx.x, 0);
}
__global__ __launch_bounds__(256) void k_ffn1t(const float* __restrict__ h1,
                                               const float* __restrict__ b1) {
    gemm_body<false, 1>(h1, g_wT + OFF_W1, b1, g_z, nullptr,
                        nullptr, nullptr, NN, HID, DIM, blockIdx.x, blockIdx.y);
}
__global__ __launch_bounds__(256) void k_ffn2t(const float* __restrict__ b2,
                                               const float* __restrict__ gamma,
                                               const float* __restrict__ beta,
                                               float* __restrict__ io) {
    gemm_body<true, 2>(g_z, g_wT + OFF_W2, b2, nullptr, io,
                       gamma, beta, NN, DIM, HID, blockIdx.x, 0);
}

// ---------------- attention coefficients (fp16 h) -----------------------------
__global__ void k_attn(const float* __restrict__ att_s,
                       const float* __restrict__ att_d) {
    int idx = blockIdx.x * blockDim.x + threadIdx.x;
    if (idx >= NN * HEADS) return;
    int n = idx >> 3, hh = idx & 7;
    const __half* hr = &g_h16[(size_t)n * DIM + hh * 16];
    float s1 = 0.f, s2 = 0.f;
    #pragma unroll
    for (int k = 0; k < 8; ++k) {
        float2 hv = __half22float2(*(const __half2*)&hr[k * 2]);
        s1 = fmaf(hv.x, att_s[hh * 16 + k * 2],     s1);
        s1 = fmaf(hv.y, att_s[hh * 16 + k * 2 + 1], s1);
        s2 = fmaf(hv.x, att_d[hh * 16 + k * 2],     s2);
        s2 = fmaf(hv.y, att_d[hh * 16 + k * 2 + 1], s2);
    }
    g_asrc[idx] = s1;
    g_adst[idx] = s2;
}

// -------- single-pass aggregation + residual + LN1 (1 warp / node) -----------
__device__ __forceinline__ float leaky(float v) { return fmaxf(v, NEG * v); }

__global__ __launch_bounds__(256) void k_agg_ln(
    const float* __restrict__ x, const float* __restrict__ bg,
    const float* __restrict__ gamma, const float* __restrict__ beta,
    float* __restrict__ h1)
{
    int w = (blockIdx.x * blockDim.x + threadIdx.x) >> 5;
    if (w >= NN) return;
    const int lane = threadIdx.x & 31;
    const int myh = lane >> 2;

    const float adm  = g_adst[w * 8 + myh];
    const float asm_ = g_asrc[w * 8 + myh];

    const int beg = g_offsets[w];
    const int end = g_offsets[w + 1];

    float l = 0.f;
    float a0 = 0.f, a1 = 0.f, a2 = 0.f, a3 = 0.f;
    {   // self loop
        float p = __expf(leaky(asm_ + adm));
        l += p;
        uint2 u = *(const uint2*)&g_h16[(size_t)w * DIM + lane * 4];
        float2 h0 = __half22float2(*(__half2*)&u.x);
        float2 h1v = __half22float2(*(__half2*)&u.y);
        a0 += p * h0.x; a1 += p * h0.y; a2 += p * h1v.x; a3 += p * h1v.y;
    }
    int j = beg;
    for (; j + 3 < end; j += 4) {
        int s0 = g_csr[j],     s1 = g_csr[j + 1];
        int s2 = g_csr[j + 2], s3 = g_csr[j + 3];
        float p0 = __expf(leaky(g_asrc[s0 * 8 + myh] + adm));
        float p1 = __expf(leaky(g_asrc[s1 * 8 + myh] + adm));
        float p2 = __expf(leaky(g_asrc[s2 * 8 + myh] + adm));
        float p3 = __expf(leaky(g_asrc[s3 * 8 + myh] + adm));
        uint2 u0 = *(const uint2*)&g_h16[(size_t)s0 * DIM + lane * 4];
        uint2 u1 = *(const uint2*)&g_h16[(size_t)s1 * DIM + lane * 4];
        uint2 u2 = *(const uint2*)&g_h16[(size_t)s2 * DIM + lane * 4];
        uint2 u3 = *(const uint2*)&g_h16[(size_t)s3 * DIM + lane * 4];
        l += p0 + p1 + p2 + p3;
        float2 q0 = __half22float2(*(__half2*)&u0.x);
        float2 q1 = __half22float2(*(__half2*)&u0.y);
        float2 r0 = __half22float2(*(__half2*)&u1.x);
        float2 r1 = __half22float2(*(__half2*)&u1.y);
        float2 t0 = __half22float2(*(__half2*)&u2.x);
        float2 t1 = __half22float2(*(__half2*)&u2.y);
        float2 v0 = __half22float2(*(__half2*)&u3.x);
        float2 v1 = __half22float2(*(__half2*)&u3.y);
        a0 += p0 * q0.x + p1 * r0.x + p2 * t0.x + p3 * v0.x;
        a1 += p0 * q0.y + p1 * r0.y + p2 * t0.y + p3 * v0.y;
        a2 += p0 * q1.x + p1 * r1.x + p2 * t1.x + p3 * v1.x;
        a3 += p0 * q1.y + p1 * r1.y + p2 * t1.y + p3 * v1.y;
    }
    for (; j < end; ++j) {
        int s = g_csr[j];
        float p = __expf(leaky(g_asrc[s * 8 + myh] + adm));
        l += p;
        uint2 u = *(const uint2*)&g_h16[(size_t)s * DIM + lane * 4];
        float2 h0 = __half22float2(*(__half2*)&u.x);
        float2 h1v = __half22float2(*(__half2*)&u.y);
        a0 += p * h0.x; a1 += p * h0.y; a2 += p * h1v.x; a3 += p * h1v.y;
    }
    float inv = 1.f / (l + 1e-16f);

    float4 xv  = *(const float4*)&x[(size_t)w * DIM + lane * 4];
    float4 bgv = *(const float4*)&bg[lane * 4];
    float4 v;
    v.x = xv.x + a0 * inv + bgv.x;
    v.y = xv.y + a1 * inv + bgv.y;
    v.z = xv.z + a2 * inv + bgv.z;
    v.w = xv.w + a3 * inv + bgv.w;

    float s = v.x + v.y + v.z + v.w;
    #pragma unroll
    for (int o = 16; o > 0; o >>= 1) s += __shfl_xor_sync(0xFFFFFFFFu, s, o);
    float mu = s * (1.f / DIM);
    v.x -= mu; v.y -= mu; v.z -= mu; v.w -= mu;
    float q = v.x * v.x + v.y * v.y + v.z * v.z + v.w * v.w;
    #pragma unroll
    for (int o = 16; o > 0; o >>= 1) q += __shfl_xor_sync(0xFFFFFFFFu, q, o);
    float rs = rsqrtf(q * (1.f / DIM) + LNEPS);
    float4 g  = *(const float4*)&gamma[lane * 4];
    float4 be = *(const float4*)&beta[lane * 4];
    float4 o4;
    o4.x = g.x * v.x * rs + be.x;
    o4.y = g.y * v.y * rs + be.y;
    o4.z = g.z * v.z * rs + be.z;
    o4.w = g.w * v.w * rs + be.w;
    *(float4*)&h1[(size_t)w * DIM + lane * 4] = o4;
}

// ---------------- launcher: forked capture branches ---------------------------
extern "C" void kernel_launch(void* const* d_in, const int* in_sizes, int n_in,
                              void* d_out, int out_size)
{
    const float* x     = (const float*)d_in[0];
    const void*  ei    = d_in[1];
    const float* Wg    = (const float*)d_in[2];
    const float* att_s = (const float*)d_in[3];
    const float* att_d = (const float*)d_in[4];
    const float* bg    = (const float*)d_in[5];
    const float* gamma = (const float*)d_in[6];
    const float* beta  = (const float*)d_in[7];
    const float* W1    = (const float*)d_in[8];
    const float* b1    = (const float*)d_in[9];
    const float* W2    = (const float*)d_in[10];
    const float* b2    = (const float*)d_in[11];
    float*       out   = (float*)d_out;

    // side stream + fork/join events (leaked: never destroyed — capture-safe;
    // kernel_launch is invoked only a handful of times by the harness)
    cudaStream_t sB;
    cudaStreamCreateWithFlags(&sB, cudaStreamNonBlocking);
    cudaEvent_t evFork, evJoin;
    cudaEventCreateWithFlags(&evFork, cudaEventDisableTiming);
    cudaEventCreateWithFlags(&evJoin, cudaEventDisableTiming);

    cudaEventRecord(evFork, 0);
    cudaStreamWaitEvent(sB, evFork, 0);

    // ---- Branch A (main stream): edge/CSR pipeline
    k_prep<<<(NN + 255) / 256, 256>>>((const unsigned int*)ei);
    k_hist<<<(NE + 255) / 256, 256>>>(ei);
    k_scan_part<<<SCAN_NB, 1024>>>();
    k_scan_tops<<<1, 128>>>();
    k_scan_add<<<SCAN_NB, 1024>>>();
    k_scatter<<<(NE + 255) / 256, 256>>>(ei);

    // ---- Branch B (side stream): weights + feature GEMM + attn coefficients
    k_convT_all<<<(WTOT + 255) / 256, 256, 0, sB>>>(Wg, W1, W2);
    k_gemm1<<<GB_ROWS, 256, 0, sB>>>(x);
    k_attn<<<(NN * HEADS + 255) / 256, 256, 0, sB>>>(att_s, att_d);

    cudaEventRecord(evJoin, sB);
    cudaStreamWaitEvent(0, evJoin, 0);

    // ---- Joined tail
    k_agg_ln<<<(NN * 32 + 255) / 256, 256>>>(x, bg, gamma, beta, out);
    k_ffn1t<<<dim3(GB_ROWS, HID / 128), 256>>>(out, b1);
    k_ffn2t<<<GB_ROWS, 256>>>(b2, gamma, beta, out);
}